// round 6
// baseline (speedup 1.0000x reference)
#include <cuda_runtime.h>

#define BB 4096
#define SS 128
#define EH 128
#define DH 256
#define NDEC 10

typedef unsigned long long u64;

__device__ float g_ctx[BB * EH];

__device__ __forceinline__ void ffma2(u64 a, u64 b, u64& c) {
    asm("fma.rn.f32x2 %0, %1, %2, %0;" : "+l"(c) : "l"(a), "l"(b));
}
__device__ __forceinline__ float f2sum(u64 a) {
    float lo = __int_as_float((unsigned)(a & 0xffffffffULL));
    float hi = __int_as_float((unsigned)(a >> 32));
    return lo + hi;
}
__device__ __forceinline__ float sigf(float v) {
    return __fdividef(1.f, 1.f + __expf(-v));
}
__device__ __forceinline__ float tanhfast(float v) {
    float e = __expf(2.f * v);
    return 1.f - __fdividef(2.f, e + 1.f);
}
__device__ __forceinline__ unsigned smem_u32(const void* p) {
    return (unsigned)__cvta_generic_to_shared(p);
}
__device__ __forceinline__ void mbar_init(unsigned a, unsigned cnt) {
    asm volatile("mbarrier.init.shared.b64 [%0], %1;" :: "r"(a), "r"(cnt) : "memory");
}
__device__ __forceinline__ void mbar_arrive(unsigned a) {
    asm volatile("mbarrier.arrive.shared.b64 _, [%0];" :: "r"(a) : "memory");
}
__device__ __forceinline__ void mbar_wait(unsigned a, unsigned ph) {
    asm volatile(
        "{\n\t.reg .pred P;\n"
        "MW_%=:\n\t"
        "mbarrier.try_wait.parity.acquire.cta.shared::cta.b64 P, [%0], %1, 0x989680;\n\t"
        "@!P bra MW_%=;\n\t}"
        :: "r"(a), "r"(ph) : "memory");
}
__device__ __forceinline__ void barc() {   // compute-warps-only barrier (256 thr)
    asm volatile("bar.sync 1, 256;" ::: "memory");
}

// ---------------------------------------------------------------------------
// Encoder: unchanged R4 baseline (~1220us). 128 blocks x 256 threads.
// ---------------------------------------------------------------------------
#define E_WSTR 132
#define E_SMEM_FLOATS (384 * E_WSTR + 32 * 128 + 384 * 5 + 384 + 384 + 160)
#define E_SMEM_BYTES (E_SMEM_FLOATS * 4)

__global__ void __launch_bounds__(256, 1)
enc_kernel(const float* __restrict__ x, const float* __restrict__ Wih,
           const float* __restrict__ Whh, const float* __restrict__ bih,
           const float* __restrict__ bhh)
{
    extern __shared__ float sm[];
    float* Whh_s = sm;
    float* h_s   = Whh_s + 384 * E_WSTR;
    float* Wih_s = h_s + 32 * 128;
    float* bih_s = Wih_s + 384 * 5;
    float* bhh_s = bih_s + 384;
    float* x_s   = bhh_s + 384;

    const int tid = threadIdx.x;
    const int b0 = blockIdx.x * 32;

    for (int u = tid; u < 384 * 32; u += 256) {
        int c = u >> 5, q = u & 31;
        *(float4*)(Whh_s + c * E_WSTR + q * 4) =
            *(const float4*)(Whh + c * 128 + q * 4);
    }
    for (int u = tid; u < 384 * 5; u += 256) Wih_s[u] = Wih[u];
    for (int u = tid; u < 384; u += 256) {
        bih_s[u] = bih[u];
        bhh_s[u] = bhh[u];
    }
    for (int u = tid; u < 32 * 128; u += 256) h_s[u] = 0.f;
    if (tid < 160)
        x_s[tid] = x[(long)(b0 + tid / 5) * (SS * 5) + (tid % 5)];
    __syncthreads();

    const int rg = tid >> 6;
    const int cg = tid & 63;
    const int r0 = rg * 8;
    int col[6];
#pragma unroll
    for (int m = 0; m < 6; m++) col[m] = cg + m * 64;
    const float* wp[6];
#pragma unroll
    for (int m = 0; m < 6; m++) wp[m] = Whh_s + col[m] * E_WSTR;

    for (int t = 0; t < SS; ++t) {
        u64 acc[8][6];
#pragma unroll
        for (int i = 0; i < 8; i++)
#pragma unroll
            for (int m = 0; m < 6; m++) acc[i][m] = 0ULL;

#pragma unroll 2
        for (int kq = 0; kq < 32; ++kq) {
            ulonglong2 w2[6];
#pragma unroll
            for (int m = 0; m < 6; m++)
                w2[m] = *(const ulonglong2*)(wp[m] + kq * 4);
#pragma unroll
            for (int i = 0; i < 8; i++) {
                ulonglong2 hv = *(const ulonglong2*)(h_s + (r0 + i) * 128 + kq * 4);
#pragma unroll
                for (int m = 0; m < 6; m++) {
                    ffma2(hv.x, w2[m].x, acc[i][m]);
                    ffma2(hv.y, w2[m].y, acc[i][m]);
                }
            }
        }

        float hnew[8][2];
#pragma unroll
        for (int i = 0; i < 8; i++) {
            float xv[5];
#pragma unroll
            for (int j = 0; j < 5; j++) xv[j] = x_s[(r0 + i) * 5 + j];
#pragma unroll
            for (int cc = 0; cc < 2; ++cc) {
                int cr = col[cc], cz = col[cc + 2], cn = col[cc + 4];
                float gir = bih_s[cr], giz = bih_s[cz], gin = bih_s[cn];
#pragma unroll
                for (int j = 0; j < 5; j++) {
                    gir += xv[j] * Wih_s[cr * 5 + j];
                    giz += xv[j] * Wih_s[cz * 5 + j];
                    gin += xv[j] * Wih_s[cn * 5 + j];
                }
                float ghr = f2sum(acc[i][cc])     + bhh_s[cr];
                float ghz = f2sum(acc[i][cc + 2]) + bhh_s[cz];
                float ghn = f2sum(acc[i][cc + 4]) + bhh_s[cn];
                float rr = sigf(gir + ghr);
                float zz = sigf(giz + ghz);
                float nn = tanhfast(gin + rr * ghn);
                float hold = h_s[(r0 + i) * 128 + col[cc]];
                hnew[i][cc] = (1.f - zz) * nn + zz * hold;
            }
        }
        __syncthreads();
#pragma unroll
        for (int i = 0; i < 8; i++) {
            h_s[(r0 + i) * 128 + col[0]] = hnew[i][0];
            h_s[(r0 + i) * 128 + col[1]] = hnew[i][1];
        }
        if (t + 1 < SS && tid < 160)
            x_s[tid] = x[(long)(b0 + tid / 5) * (SS * 5) + (t + 1) * 5 + (tid % 5)];
        __syncthreads();
    }

    for (int u = tid; u < 32 * 32; u += 256) {
        int r = u >> 5, q = u & 31;
        *(float4*)(g_ctx + (long)(b0 + r) * 128 + q * 4) =
            *(float4*)(h_s + r * 128 + q * 4);
    }
}

// ---------------------------------------------------------------------------
// Decoder: warp-specialized. 256 blocks x 320 threads (8 compute + 2 producer
// warps), 16 batch rows per block.
// Compute thread T owns gate triple (T, T+256, T+512) x ALL 16 rows
// (single-reader weights -> halved weight LDS wavefronts).
// Producer warps stream k=16 weight chunks (stride 20, conflict-free) through
// a 2-stage mbarrier ring. No block-wide barriers in the k loop.
// ---------------------------------------------------------------------------
#define DSTG (768 * 20)   // floats per ring stage
#define D_SMEM_FLOATS (2 * DSTG + 16 * 768 + 16 * 256 + 768 + 768 + 1024 + 4 + 160 + 8)
#define D_SMEM_BYTES (D_SMEM_FLOATS * 4)

__global__ void __launch_bounds__(320, 1)
dec_kernel(const float* __restrict__ y, const float* __restrict__ Wih,
           const float* __restrict__ Whh, const float* __restrict__ bih,
           const float* __restrict__ bhh, const float* __restrict__ linW,
           const float* __restrict__ linb, float* __restrict__ out)
{
    extern __shared__ float sm[];
    float* ring  = sm;                       // 2 * 768*20
    float* gi_s  = ring + 2 * DSTG;          // 16*768
    float* h2_s  = gi_s + 16 * 768;          // 16*256
    float* wy_s  = h2_s + 16 * 256;          // 768
    float* bhh_s = wy_s + 768;               // 768
    float* lw_s  = bhh_s + 768;              // 1024
    float* lb_s  = lw_s + 1024;              // 4
    float* y_s   = lb_s + 4;                 // 160
    float* mb_f  = y_s + 160;                // 4 mbarriers (8 floats)

    const int tid = threadIdx.x;
    const int b0 = blockIdx.x * 16;

    const unsigned mb_full0  = smem_u32(mb_f);
    const unsigned mb_empty0 = mb_full0 + 16;   // full[0],full[1],empty[0],empty[1]

    if (tid == 0) {
        mbar_init(mb_full0, 64);        // full[0]
        mbar_init(mb_full0 + 8, 64);    // full[1]
        mbar_init(mb_empty0, 256);      // empty[0]
        mbar_init(mb_empty0 + 8, 256);  // empty[1]
    }

    // fill out[:, 10:, :] = 1 for our 16 rows
    {
        const float4 one4 = make_float4(1.f, 1.f, 1.f, 1.f);
        for (int u = tid; u < 16 * 118; u += 320) {
            int r = u / 118, tt = u % 118 + NDEC;
            *(float4*)(out + (long)(b0 + r) * (SS * 4) + tt * 4) = one4;
        }
    }
    for (int u = tid; u < 768; u += 320) {
        wy_s[u]  = Wih[(long)u * 129 + 128];
        bhh_s[u] = bhh[u];
    }
    for (int u = tid; u < 1024; u += 320) lw_s[u] = linW[u];
    if (tid < 4) lb_s[tid] = linb[tid];
    if (tid < 160) {
        int r = tid / 10, t = tid % 10;
        y_s[tid] = y[(long)(b0 + r) * SS + t];
    }
    // stage context into h2_s (16 rows x 128, stride 256)
    for (int u = tid; u < 16 * 32; u += 320) {
        int r = u >> 5, q = u & 31;
        *(float4*)(h2_s + r * 256 + q * 4) =
            *(const float4*)(g_ctx + (long)(b0 + r) * 128 + q * 4);
    }
    __syncthreads();   // mbarriers initialized + staging visible; roles split now

    if (tid >= 256) {
        // ---------------- producer: 2 warps stream weight chunks ------------
        const int pt = tid - 256;   // 0..63
        int s = 0;
        unsigned pe = 1;            // phase trick: first empty-wait passes
        // 8 chunks of dec_Wih[:, 0:128] (row stride 129, scalar loads)
        for (int kc = 0; kc < 8; ++kc) {
            mbar_wait(mb_empty0 + s * 8, pe);
            float* dst = ring + s * DSTG;
            const float* src = Wih + kc * 16;
            for (int u = pt; u < 768 * 16; u += 64) {
                int c = u >> 4, q = u & 15;
                dst[c * 20 + q] = src[(long)c * 129 + q];
            }
            mbar_arrive(mb_full0 + s * 8);
            if (++s == 2) { s = 0; pe ^= 1; }
        }
        // 10 steps x 16 chunks of dec_Whh (row stride 256, float4 loads)
        for (int n = 0; n < NDEC * 16; ++n) {
            int kc = n & 15;
            mbar_wait(mb_empty0 + s * 8, pe);
            float* dst = ring + s * DSTG;
            const float* src = Whh + kc * 16;
            for (int u = pt; u < 768 * 4; u += 64) {
                int c = u >> 2, q = u & 3;
                *(float4*)(dst + c * 20 + q * 4) =
                    *(const float4*)(src + (long)c * 256 + q * 4);
            }
            mbar_arrive(mb_full0 + s * 8);
            if (++s == 2) { s = 0; pe ^= 1; }
        }
        return;
    }

    // ------------------- consumer: 8 compute warps --------------------------
    const int T = tid;              // 0..255
    const int c0 = T, c1 = T + 256, c2 = T + 512;
    int s = 0;
    unsigned pf = 0;

    // gi_ctx = bih + ctx @ Wih[:, :128]^T
    {
        u64 acc[16][3];
#pragma unroll
        for (int i = 0; i < 16; i++)
#pragma unroll
            for (int m = 0; m < 3; m++) acc[i][m] = 0ULL;
        for (int kc = 0; kc < 8; ++kc) {
            mbar_wait(mb_full0 + s * 8, pf);
            const float* wb = ring + s * DSTG;
#pragma unroll
            for (int kq = 0; kq < 4; ++kq) {
                ulonglong2 w0 = *(const ulonglong2*)(wb + c0 * 20 + kq * 4);
                ulonglong2 w1 = *(const ulonglong2*)(wb + c1 * 20 + kq * 4);
                ulonglong2 w2 = *(const ulonglong2*)(wb + c2 * 20 + kq * 4);
#pragma unroll
                for (int i = 0; i < 16; i++) {
                    ulonglong2 hv =
                        *(const ulonglong2*)(h2_s + i * 256 + kc * 16 + kq * 4);
                    ffma2(hv.x, w0.x, acc[i][0]);
                    ffma2(hv.y, w0.y, acc[i][0]);
                    ffma2(hv.x, w1.x, acc[i][1]);
                    ffma2(hv.y, w1.y, acc[i][1]);
                    ffma2(hv.x, w2.x, acc[i][2]);
                    ffma2(hv.y, w2.y, acc[i][2]);
                }
            }
            mbar_arrive(mb_empty0 + s * 8);
            if (++s == 2) { s = 0; pf ^= 1; }
        }
        float b0r = bih[c0], b1z = bih[c1], b2n = bih[c2];
#pragma unroll
        for (int i = 0; i < 16; i++) {
            gi_s[i * 768 + c0] = f2sum(acc[i][0]) + b0r;
            gi_s[i * 768 + c1] = f2sum(acc[i][1]) + b1z;
            gi_s[i * 768 + c2] = f2sum(acc[i][2]) + b2n;
        }
    }
    barc();                          // all ctx reads of h2_s done
#pragma unroll
    for (int i = 0; i < 16; i++) h2_s[i * 256 + T] = 1.f;   // h_dec0 = ones
    barc();

    const float bhr = bhh_s[c0], bhz = bhh_s[c1], bhn = bhh_s[c2];
    const float wyr = wy_s[c0],  wyz = wy_s[c1],  wyn = wy_s[c2];

    for (int t = 0; t < NDEC; ++t) {
        u64 acc[16][3];
#pragma unroll
        for (int i = 0; i < 16; i++)
#pragma unroll
            for (int m = 0; m < 3; m++) acc[i][m] = 0ULL;

        for (int kc = 0; kc < 16; ++kc) {
            mbar_wait(mb_full0 + s * 8, pf);
            const float* wb = ring + s * DSTG;
#pragma unroll
            for (int kq = 0; kq < 4; ++kq) {
                ulonglong2 w0 = *(const ulonglong2*)(wb + c0 * 20 + kq * 4);
                ulonglong2 w1 = *(const ulonglong2*)(wb + c1 * 20 + kq * 4);
                ulonglong2 w2 = *(const ulonglong2*)(wb + c2 * 20 + kq * 4);
#pragma unroll
                for (int i = 0; i < 16; i++) {
                    ulonglong2 hv =
                        *(const ulonglong2*)(h2_s + i * 256 + kc * 16 + kq * 4);
                    ffma2(hv.x, w0.x, acc[i][0]);
                    ffma2(hv.y, w0.y, acc[i][0]);
                    ffma2(hv.x, w1.x, acc[i][1]);
                    ffma2(hv.y, w1.y, acc[i][1]);
                    ffma2(hv.x, w2.x, acc[i][2]);
                    ffma2(hv.y, w2.y, acc[i][2]);
                }
            }
            mbar_arrive(mb_empty0 + s * 8);
            if (++s == 2) { s = 0; pf ^= 1; }
        }

        float hnew[16];
#pragma unroll
        for (int i = 0; i < 16; i++) {
            float yv = y_s[i * 10 + t];
            float gir = gi_s[i * 768 + c0] + yv * wyr;
            float giz = gi_s[i * 768 + c1] + yv * wyz;
            float gin = gi_s[i * 768 + c2] + yv * wyn;
            float ghr = f2sum(acc[i][0]) + bhr;
            float ghz = f2sum(acc[i][1]) + bhz;
            float ghn = f2sum(acc[i][2]) + bhn;
            float rr = sigf(gir + ghr);
            float zz = sigf(giz + ghz);
            float nn = tanhfast(gin + rr * ghn);
            hnew[i] = (1.f - zz) * nn + zz * h2_s[i * 256 + T];
        }
        barc();                      // all k-loop reads of h2_s done
#pragma unroll
        for (int i = 0; i < 16; i++) h2_s[i * 256 + T] = hnew[i];
        barc();                      // new h visible

        if (T < 64) {
            int r = T >> 2, o = T & 3;
            float sacc = lb_s[o];
#pragma unroll 4
            for (int q = 0; q < 64; ++q) {
                float4 hv = *(float4*)(h2_s + r * 256 + q * 4);
                float4 wv = *(float4*)(lw_s + o * 256 + q * 4);
                sacc += hv.x * wv.x + hv.y * wv.y + hv.z * wv.z + hv.w * wv.w;
            }
            out[(long)(b0 + r) * (SS * 4) + t * 4 + o] = sacc;
        }
    }
}

extern "C" void kernel_launch(void* const* d_in, const int* in_sizes, int n_in,
                              void* d_out, int out_size) {
    const float* x    = (const float*)d_in[0];
    const float* y    = (const float*)d_in[1];
    const float* eWih = (const float*)d_in[2];
    const float* eWhh = (const float*)d_in[3];
    const float* ebih = (const float*)d_in[4];
    const float* ebhh = (const float*)d_in[5];
    const float* dWih = (const float*)d_in[6];
    const float* dWhh = (const float*)d_in[7];
    const float* dbih = (const float*)d_in[8];
    const float* dbhh = (const float*)d_in[9];
    const float* lW   = (const float*)d_in[10];
    const float* lb   = (const float*)d_in[11];
    float* out = (float*)d_out;

    cudaFuncSetAttribute(enc_kernel, cudaFuncAttributeMaxDynamicSharedMemorySize,
                         E_SMEM_BYTES);
    cudaFuncSetAttribute(dec_kernel, cudaFuncAttributeMaxDynamicSharedMemorySize,
                         D_SMEM_BYTES);

    enc_kernel<<<BB / 32, 256, E_SMEM_BYTES>>>(x, eWih, eWhh, ebih, ebhh);
    dec_kernel<<<BB / 16, 320, D_SMEM_BYTES>>>(y, dWih, dWhh, dbih, dbhh, lW, lb, out);
}

// round 7
// speedup vs baseline: 1.3012x; 1.3012x over previous
#include <cuda_runtime.h>

#define BB 4096
#define SS 128
#define EH 128
#define DH 256
#define NDEC 10

typedef unsigned long long u64;

// encoder -> decoder context
__device__ float g_ctx[BB * EH];
// decoder scratch (L2-resident working set)
__device__ float g_gates[BB * 768];   // h @ Whh^T per step
__device__ float g_gi0[BB * 768];     // bih + ctx @ Wih[:, :128]^T
__device__ float g_h[BB * DH];        // decoder hidden state

__device__ __forceinline__ void ffma2(u64 a, u64 b, u64& c) {
    asm("fma.rn.f32x2 %0, %1, %2, %0;" : "+l"(c) : "l"(a), "l"(b));
}
__device__ __forceinline__ float f2sum(u64 a) {
    float lo = __int_as_float((unsigned)(a & 0xffffffffULL));
    float hi = __int_as_float((unsigned)(a >> 32));
    return lo + hi;
}
__device__ __forceinline__ float sigf(float v) {
    return __fdividef(1.f, 1.f + __expf(-v));
}
__device__ __forceinline__ float tanhfast(float v) {
    float e = __expf(2.f * v);
    return 1.f - __fdividef(2.f, e + 1.f);
}

// ---------------------------------------------------------------------------
// Encoder: R4 baseline, unchanged (~1220us; at scalar roofline).
// ---------------------------------------------------------------------------
#define E_WSTR 132
#define E_SMEM_FLOATS (384 * E_WSTR + 32 * 128 + 384 * 5 + 384 + 384 + 160)
#define E_SMEM_BYTES (E_SMEM_FLOATS * 4)

__global__ void __launch_bounds__(256, 1)
enc_kernel(const float* __restrict__ x, const float* __restrict__ Wih,
           const float* __restrict__ Whh, const float* __restrict__ bih,
           const float* __restrict__ bhh)
{
    extern __shared__ float sm[];
    float* Whh_s = sm;
    float* h_s   = Whh_s + 384 * E_WSTR;
    float* Wih_s = h_s + 32 * 128;
    float* bih_s = Wih_s + 384 * 5;
    float* bhh_s = bih_s + 384;
    float* x_s   = bhh_s + 384;

    const int tid = threadIdx.x;
    const int b0 = blockIdx.x * 32;

    for (int u = tid; u < 384 * 32; u += 256) {
        int c = u >> 5, q = u & 31;
        *(float4*)(Whh_s + c * E_WSTR + q * 4) =
            *(const float4*)(Whh + c * 128 + q * 4);
    }
    for (int u = tid; u < 384 * 5; u += 256) Wih_s[u] = Wih[u];
    for (int u = tid; u < 384; u += 256) {
        bih_s[u] = bih[u];
        bhh_s[u] = bhh[u];
    }
    for (int u = tid; u < 32 * 128; u += 256) h_s[u] = 0.f;
    if (tid < 160)
        x_s[tid] = x[(long)(b0 + tid / 5) * (SS * 5) + (tid % 5)];
    __syncthreads();

    const int rg = tid >> 6;
    const int cg = tid & 63;
    const int r0 = rg * 8;
    int col[6];
#pragma unroll
    for (int m = 0; m < 6; m++) col[m] = cg + m * 64;
    const float* wp[6];
#pragma unroll
    for (int m = 0; m < 6; m++) wp[m] = Whh_s + col[m] * E_WSTR;

    for (int t = 0; t < SS; ++t) {
        u64 acc[8][6];
#pragma unroll
        for (int i = 0; i < 8; i++)
#pragma unroll
            for (int m = 0; m < 6; m++) acc[i][m] = 0ULL;

#pragma unroll 2
        for (int kq = 0; kq < 32; ++kq) {
            ulonglong2 w2[6];
#pragma unroll
            for (int m = 0; m < 6; m++)
                w2[m] = *(const ulonglong2*)(wp[m] + kq * 4);
#pragma unroll
            for (int i = 0; i < 8; i++) {
                ulonglong2 hv = *(const ulonglong2*)(h_s + (r0 + i) * 128 + kq * 4);
#pragma unroll
                for (int m = 0; m < 6; m++) {
                    ffma2(hv.x, w2[m].x, acc[i][m]);
                    ffma2(hv.y, w2[m].y, acc[i][m]);
                }
            }
        }

        float hnew[8][2];
#pragma unroll
        for (int i = 0; i < 8; i++) {
            float xv[5];
#pragma unroll
            for (int j = 0; j < 5; j++) xv[j] = x_s[(r0 + i) * 5 + j];
#pragma unroll
            for (int cc = 0; cc < 2; ++cc) {
                int cr = col[cc], cz = col[cc + 2], cn = col[cc + 4];
                float gir = bih_s[cr], giz = bih_s[cz], gin = bih_s[cn];
#pragma unroll
                for (int j = 0; j < 5; j++) {
                    gir += xv[j] * Wih_s[cr * 5 + j];
                    giz += xv[j] * Wih_s[cz * 5 + j];
                    gin += xv[j] * Wih_s[cn * 5 + j];
                }
                float ghr = f2sum(acc[i][cc])     + bhh_s[cr];
                float ghz = f2sum(acc[i][cc + 2]) + bhh_s[cz];
                float ghn = f2sum(acc[i][cc + 4]) + bhh_s[cn];
                float rr = sigf(gir + ghr);
                float zz = sigf(giz + ghz);
                float nn = tanhfast(gin + rr * ghn);
                float hold = h_s[(r0 + i) * 128 + col[cc]];
                hnew[i][cc] = (1.f - zz) * nn + zz * hold;
            }
        }
        __syncthreads();
#pragma unroll
        for (int i = 0; i < 8; i++) {
            h_s[(r0 + i) * 128 + col[0]] = hnew[i][0];
            h_s[(r0 + i) * 128 + col[1]] = hnew[i][1];
        }
        if (t + 1 < SS && tid < 160)
            x_s[tid] = x[(long)(b0 + tid / 5) * (SS * 5) + (t + 1) * 5 + (tid % 5)];
        __syncthreads();
    }

    for (int u = tid; u < 32 * 32; u += 256) {
        int r = u >> 5, q = u & 31;
        *(float4*)(g_ctx + (long)(b0 + r) * 128 + q * 4) =
            *(float4*)(h_s + r * 128 + q * 4);
    }
}

// ---------------------------------------------------------------------------
// init: h_dec = ones, out[:, 10:, :] = ones
// ---------------------------------------------------------------------------
__global__ void init_kernel(float* __restrict__ out) {
    const float4 one4 = make_float4(1.f, 1.f, 1.f, 1.f);
    int i = blockIdx.x * blockDim.x + threadIdx.x;
    if (i < BB * DH / 4) ((float4*)g_h)[i] = one4;
    if (i < BB * 118) {
        int b = i / 118, tt = i % 118 + NDEC;
        *(float4*)(out + (long)b * (SS * 4) + tt * 4) = one4;
    }
}

// ---------------------------------------------------------------------------
// Decoder GEMM slice kernels. Grid = 6 slices x 24 batch groups = 144 blocks.
// Slice s holds W[s*128:(s+1)*128, :K] resident in SMEM (conflict-free pad).
// Batch group g owns rows [g*171, ...) (last group 163). Rows processed in
// 64-row chunks staged in SMEM. Thread tile: 8 rows x 4 cols. No barriers in
// the k-loop; 1 barrier per 64-row chunk.
// ---------------------------------------------------------------------------
#define NG 24
#define RPG 171

// gi0: gates0 = bih + ctx @ Wih[:, :128]^T   (K = 128)
#define GI_WSTR 132
#define GI_SMEM_BYTES ((128 * GI_WSTR + 64 * 128) * 4)

__global__ void __launch_bounds__(256, 1)
dec_gi0_kernel(const float* __restrict__ Wih, const float* __restrict__ bih)
{
    extern __shared__ float sm[];
    float* Ws = sm;                    // 128 cols x GI_WSTR
    float* hs = sm + 128 * GI_WSTR;    // 64 rows x 128

    const int tid = threadIdx.x;
    const int s = blockIdx.x / NG;
    const int g = blockIdx.x % NG;
    const int r0 = g * RPG;
    const int nr = min(RPG, BB - r0);

    for (int u = tid; u < 128 * 128; u += 256) {
        int c = u >> 7, k = u & 127;
        Ws[c * GI_WSTR + k] = Wih[(long)(s * 128 + c) * 129 + k];
    }
    __syncthreads();

    const int rg = tid >> 5, cg = tid & 31;
    float bv[4];
#pragma unroll
    for (int m = 0; m < 4; m++) bv[m] = bih[s * 128 + cg + 32 * m];

    const int nchunk = (nr + 63) >> 6;
    for (int ch = 0; ch < nchunk; ++ch) {
        int rbase = ch * 64;
        for (int u = tid; u < 64 * 32; u += 256) {
            int r = u >> 5, q = u & 31;
            float4 v = make_float4(0.f, 0.f, 0.f, 0.f);
            if (rbase + r < nr)
                v = *(const float4*)(g_ctx + (long)(r0 + rbase + r) * 128 + q * 4);
            *(float4*)(hs + r * 128 + q * 4) = v;
        }
        __syncthreads();

        u64 acc[8][4];
#pragma unroll
        for (int i = 0; i < 8; i++)
#pragma unroll
            for (int m = 0; m < 4; m++) acc[i][m] = 0ULL;

#pragma unroll 2
        for (int kq = 0; kq < 32; ++kq) {
            ulonglong2 w[4];
#pragma unroll
            for (int m = 0; m < 4; m++)
                w[m] = *(const ulonglong2*)(Ws + (cg + 32 * m) * GI_WSTR + kq * 4);
#pragma unroll
            for (int i = 0; i < 8; i++) {
                ulonglong2 hv = *(const ulonglong2*)(hs + (rg * 8 + i) * 128 + kq * 4);
#pragma unroll
                for (int m = 0; m < 4; m++) {
                    ffma2(hv.x, w[m].x, acc[i][m]);
                    ffma2(hv.y, w[m].y, acc[i][m]);
                }
            }
        }
#pragma unroll
        for (int i = 0; i < 8; i++) {
            int row = rbase + rg * 8 + i;
            if (row < nr) {
#pragma unroll
                for (int m = 0; m < 4; m++)
                    g_gi0[(long)(r0 + row) * 768 + s * 128 + cg + 32 * m] =
                        f2sum(acc[i][m]) + bv[m];
            }
        }
        __syncthreads();
    }
}

// per-step recurrent GEMM: gates = h @ Whh^T   (K = 256)
#define A_WSTR 260
#define A_SMEM_BYTES ((128 * A_WSTR + 64 * 256) * 4)

__global__ void __launch_bounds__(256, 1)
dec_gemm_kernel(const float* __restrict__ Whh)
{
    extern __shared__ float sm[];
    float* Ws = sm;                    // 128 cols x A_WSTR
    float* hs = sm + 128 * A_WSTR;     // 64 rows x 256

    const int tid = threadIdx.x;
    const int s = blockIdx.x / NG;
    const int g = blockIdx.x % NG;
    const int r0 = g * RPG;
    const int nr = min(RPG, BB - r0);

    for (int u = tid; u < 128 * 64; u += 256) {
        int c = u >> 6, q = u & 63;
        *(float4*)(Ws + c * A_WSTR + q * 4) =
            *(const float4*)(Whh + (long)(s * 128 + c) * 256 + q * 4);
    }
    __syncthreads();

    const int rg = tid >> 5, cg = tid & 31;
    const int nchunk = (nr + 63) >> 6;
    for (int ch = 0; ch < nchunk; ++ch) {
        int rbase = ch * 64;
        for (int u = tid; u < 64 * 64; u += 256) {
            int r = u >> 6, q = u & 63;
            float4 v = make_float4(0.f, 0.f, 0.f, 0.f);
            if (rbase + r < nr)
                v = *(const float4*)(g_h + (long)(r0 + rbase + r) * 256 + q * 4);
            *(float4*)(hs + r * 256 + q * 4) = v;
        }
        __syncthreads();

        u64 acc[8][4];
#pragma unroll
        for (int i = 0; i < 8; i++)
#pragma unroll
            for (int m = 0; m < 4; m++) acc[i][m] = 0ULL;

#pragma unroll 2
        for (int kq = 0; kq < 64; ++kq) {
            ulonglong2 w[4];
#pragma unroll
            for (int m = 0; m < 4; m++)
                w[m] = *(const ulonglong2*)(Ws + (cg + 32 * m) * A_WSTR + kq * 4);
#pragma unroll
            for (int i = 0; i < 8; i++) {
                ulonglong2 hv = *(const ulonglong2*)(hs + (rg * 8 + i) * 256 + kq * 4);
#pragma unroll
                for (int m = 0; m < 4; m++) {
                    ffma2(hv.x, w[m].x, acc[i][m]);
                    ffma2(hv.y, w[m].y, acc[i][m]);
                }
            }
        }
#pragma unroll
        for (int i = 0; i < 8; i++) {
            int row = rbase + rg * 8 + i;
            if (row < nr) {
#pragma unroll
                for (int m = 0; m < 4; m++)
                    g_gates[(long)(r0 + row) * 768 + s * 128 + cg + 32 * m] =
                        f2sum(acc[i][m]);
            }
        }
        __syncthreads();
    }
}

// ---------------------------------------------------------------------------
// pointwise: gate fusion + h update + linear head. 128 blocks x 256 threads,
// 32 batch rows per block; thread owns h-column tid for all 32 rows.
// ---------------------------------------------------------------------------
__global__ void __launch_bounds__(256, 1)
dec_point_kernel(const float* __restrict__ y, const float* __restrict__ Wih,
                 const float* __restrict__ bhh, const float* __restrict__ linW,
                 const float* __restrict__ linb, float* __restrict__ out, int t)
{
    __shared__ float hs[32 * 256];
    __shared__ float ys[32];
    __shared__ float lw[1024];
    __shared__ float lb[4];

    const int tid = threadIdx.x;
    const int b0 = blockIdx.x * 32;

    if (tid < 32) ys[tid] = y[(long)(b0 + tid) * SS + t];
    for (int u = tid; u < 1024; u += 256) lw[u] = linW[u];
    if (tid < 4) lb[tid] = linb[tid];

    const int c = tid;
    const float wyr = Wih[(long)c * 129 + 128];
    const float wyz = Wih[(long)(c + 256) * 129 + 128];
    const float wyn = Wih[(long)(c + 512) * 129 + 128];
    const float br = bhh[c], bz = bhh[c + 256], bn = bhh[c + 512];
    __syncthreads();

#pragma unroll 4
    for (int r = 0; r < 32; ++r) {
        long b = b0 + r;
        float yv = ys[r];
        float gr  = g_gi0[b * 768 + c]       + yv * wyr + g_gates[b * 768 + c]       + br;
        float gz  = g_gi0[b * 768 + c + 256] + yv * wyz + g_gates[b * 768 + c + 256] + bz;
        float gni = g_gi0[b * 768 + c + 512] + yv * wyn;
        float gnh = g_gates[b * 768 + c + 512] + bn;
        float rr = sigf(gr);
        float zz = sigf(gz);
        float nn = tanhfast(gni + rr * gnh);
        float h  = g_h[b * 256 + c];
        float hn = (1.f - zz) * nn + zz * h;
        g_h[b * 256 + c] = hn;
        hs[r * 256 + c] = hn;
    }
    __syncthreads();

    if (tid < 128) {
        int r = tid >> 2, o = tid & 3;
        float s = lb[o];
#pragma unroll 4
        for (int q = 0; q < 64; ++q) {
            float4 hv = *(float4*)(hs + r * 256 + q * 4);
            float4 wv = *(float4*)(lw + o * 256 + q * 4);
            s += hv.x * wv.x + hv.y * wv.y + hv.z * wv.z + hv.w * wv.w;
        }
        out[(long)(b0 + r) * (SS * 4) + t * 4 + o] = s;
    }
}

extern "C" void kernel_launch(void* const* d_in, const int* in_sizes, int n_in,
                              void* d_out, int out_size) {
    const float* x    = (const float*)d_in[0];
    const float* y    = (const float*)d_in[1];
    const float* eWih = (const float*)d_in[2];
    const float* eWhh = (const float*)d_in[3];
    const float* ebih = (const float*)d_in[4];
    const float* ebhh = (const float*)d_in[5];
    const float* dWih = (const float*)d_in[6];
    const float* dWhh = (const float*)d_in[7];
    const float* dbih = (const float*)d_in[8];
    const float* dbhh = (const float*)d_in[9];
    const float* lW   = (const float*)d_in[10];
    const float* lb   = (const float*)d_in[11];
    float* out = (float*)d_out;

    cudaFuncSetAttribute(enc_kernel, cudaFuncAttributeMaxDynamicSharedMemorySize,
                         E_SMEM_BYTES);
    cudaFuncSetAttribute(dec_gi0_kernel, cudaFuncAttributeMaxDynamicSharedMemorySize,
                         GI_SMEM_BYTES);
    cudaFuncSetAttribute(dec_gemm_kernel, cudaFuncAttributeMaxDynamicSharedMemorySize,
                         A_SMEM_BYTES);

    init_kernel<<<(BB * 118 + 255) / 256, 256>>>(out);
    enc_kernel<<<BB / 32, 256, E_SMEM_BYTES>>>(x, eWih, eWhh, ebih, ebhh);
    dec_gi0_kernel<<<6 * NG, 256, GI_SMEM_BYTES>>>(dWih, dbih);
    for (int t = 0; t < NDEC; ++t) {
        dec_gemm_kernel<<<6 * NG, 256, A_SMEM_BYTES>>>(dWhh);
        dec_point_kernel<<<BB / 32, 256>>>(y, dWih, dbhh, lW, lb, out, t);
    }
}

// round 8
// speedup vs baseline: 1.3654x; 1.0494x over previous
#include <cuda_runtime.h>

#define BB 4096
#define SS 128
#define EH 128
#define DH 256
#define NDEC 10

typedef unsigned long long u64;

__device__ float g_ctx[BB * EH];
__device__ float g_gates[BB * 768];
__device__ float g_gi0[BB * 768];
__device__ float g_h[BB * DH];

__device__ __forceinline__ void ffma2(u64 a, u64 b, u64& c) {
    asm("fma.rn.f32x2 %0, %1, %2, %0;" : "+l"(c) : "l"(a), "l"(b));
}
__device__ __forceinline__ float f2sum(u64 a) {
    float lo = __int_as_float((unsigned)(a & 0xffffffffULL));
    float hi = __int_as_float((unsigned)(a >> 32));
    return lo + hi;
}
__device__ __forceinline__ float sigf(float v) {
    return __fdividef(1.f, 1.f + __expf(-v));
}
__device__ __forceinline__ float tanhfast(float v) {
    float e = __expf(2.f * v);
    return 1.f - __fdividef(2.f, e + 1.f);
}

// ---------------------------------------------------------------------------
// Encoder: persistent GRU. 147 blocks x 256 threads, 28 batch rows per block
// (uses 147/148 SMs; was 128 blocks x 32 rows -> 20 SMs idle).
// Thread owns 7 rows x 2 channels x 3 gates.
// ---------------------------------------------------------------------------
#define E_RPB 28
#define E_WSTR 132
#define E_SMEM_FLOATS (384 * E_WSTR + E_RPB * 128 + 384 * 5 + 384 + 384 + E_RPB * 5)
#define E_SMEM_BYTES (E_SMEM_FLOATS * 4)

__global__ void __launch_bounds__(256, 1)
enc_kernel(const float* __restrict__ x, const float* __restrict__ Wih,
           const float* __restrict__ Whh, const float* __restrict__ bih,
           const float* __restrict__ bhh)
{
    extern __shared__ float sm[];
    float* Whh_s = sm;
    float* h_s   = Whh_s + 384 * E_WSTR;      // 28*128
    float* Wih_s = h_s + E_RPB * 128;         // 384*5
    float* bih_s = Wih_s + 384 * 5;
    float* bhh_s = bih_s + 384;
    float* x_s   = bhh_s + 384;               // 28*5

    const int tid = threadIdx.x;
    const int b0 = blockIdx.x * E_RPB;

    for (int u = tid; u < 384 * 32; u += 256) {
        int c = u >> 5, q = u & 31;
        *(float4*)(Whh_s + c * E_WSTR + q * 4) =
            *(const float4*)(Whh + c * 128 + q * 4);
    }
    for (int u = tid; u < 384 * 5; u += 256) Wih_s[u] = Wih[u];
    for (int u = tid; u < 384; u += 256) {
        bih_s[u] = bih[u];
        bhh_s[u] = bhh[u];
    }
    for (int u = tid; u < E_RPB * 128; u += 256) h_s[u] = 0.f;
    if (tid < E_RPB * 5) {
        int b = b0 + tid / 5;
        x_s[tid] = (b < BB) ? x[(long)b * (SS * 5) + (tid % 5)] : 0.f;
    }
    __syncthreads();

    const int rg = tid >> 6;      // 0..3 (warp-uniform)
    const int cg = tid & 63;      // 0..63
    const int r0 = rg * 7;
    int col[6];
#pragma unroll
    for (int m = 0; m < 6; m++) col[m] = cg + m * 64;
    const float* wp[6];
#pragma unroll
    for (int m = 0; m < 6; m++) wp[m] = Whh_s + col[m] * E_WSTR;

    for (int t = 0; t < SS; ++t) {
        u64 acc[7][6];
#pragma unroll
        for (int i = 0; i < 7; i++)
#pragma unroll
            for (int m = 0; m < 6; m++) acc[i][m] = 0ULL;

#pragma unroll 2
        for (int kq = 0; kq < 32; ++kq) {
            ulonglong2 w2[6];
#pragma unroll
            for (int m = 0; m < 6; m++)
                w2[m] = *(const ulonglong2*)(wp[m] + kq * 4);
#pragma unroll
            for (int i = 0; i < 7; i++) {
                ulonglong2 hv = *(const ulonglong2*)(h_s + (r0 + i) * 128 + kq * 4);
#pragma unroll
                for (int m = 0; m < 6; m++) {
                    ffma2(hv.x, w2[m].x, acc[i][m]);
                    ffma2(hv.y, w2[m].y, acc[i][m]);
                }
            }
        }

        float hnew[7][2];
#pragma unroll
        for (int i = 0; i < 7; i++) {
            float xv[5];
#pragma unroll
            for (int j = 0; j < 5; j++) xv[j] = x_s[(r0 + i) * 5 + j];
#pragma unroll
            for (int cc = 0; cc < 2; ++cc) {
                int cr = col[cc], cz = col[cc + 2], cn = col[cc + 4];
                float gir = bih_s[cr], giz = bih_s[cz], gin = bih_s[cn];
#pragma unroll
                for (int j = 0; j < 5; j++) {
                    gir += xv[j] * Wih_s[cr * 5 + j];
                    giz += xv[j] * Wih_s[cz * 5 + j];
                    gin += xv[j] * Wih_s[cn * 5 + j];
                }
                float ghr = f2sum(acc[i][cc])     + bhh_s[cr];
                float ghz = f2sum(acc[i][cc + 2]) + bhh_s[cz];
                float ghn = f2sum(acc[i][cc + 4]) + bhh_s[cn];
                float rr = sigf(gir + ghr);
                float zz = sigf(giz + ghz);
                float nn = tanhfast(gin + rr * ghn);
                float hold = h_s[(r0 + i) * 128 + col[cc]];
                hnew[i][cc] = (1.f - zz) * nn + zz * hold;
            }
        }
        __syncthreads();
#pragma unroll
        for (int i = 0; i < 7; i++) {
            h_s[(r0 + i) * 128 + col[0]] = hnew[i][0];
            h_s[(r0 + i) * 128 + col[1]] = hnew[i][1];
        }
        if (t + 1 < SS && tid < E_RPB * 5) {
            int b = b0 + tid / 5;
            x_s[tid] = (b < BB) ? x[(long)b * (SS * 5) + (t + 1) * 5 + (tid % 5)] : 0.f;
        }
        __syncthreads();
    }

    for (int u = tid; u < E_RPB * 32; u += 256) {
        int r = u >> 5, q = u & 31;
        if (b0 + r < BB)
            *(float4*)(g_ctx + (long)(b0 + r) * 128 + q * 4) =
                *(float4*)(h_s + r * 128 + q * 4);
    }
}

// ---------------------------------------------------------------------------
// init: h_dec = ones, out[:, 10:, :] = ones
// ---------------------------------------------------------------------------
__global__ void init_kernel(float* __restrict__ out) {
    const float4 one4 = make_float4(1.f, 1.f, 1.f, 1.f);
    int i = blockIdx.x * blockDim.x + threadIdx.x;
    if (i < BB * DH / 4) ((float4*)g_h)[i] = one4;
    if (i < BB * 118) {
        int b = i / 118, tt = i % 118 + NDEC;
        *(float4*)(out + (long)b * (SS * 4) + tt * 4) = one4;
    }
}

// ---------------------------------------------------------------------------
// Decoder GEMM slices: 6 slices x 24 groups = 144 blocks.
// ---------------------------------------------------------------------------
#define NG 24
#define RPG 171

// gi0 (once): gates0 = bih + ctx @ Wih[:, :128]^T   (K = 128)
#define GI_WSTR 132
#define GI_SMEM_BYTES ((128 * GI_WSTR + 64 * 128) * 4)

__global__ void __launch_bounds__(256, 1)
dec_gi0_kernel(const float* __restrict__ Wih, const float* __restrict__ bih)
{
    extern __shared__ float sm[];
    float* Ws = sm;
    float* hs = sm + 128 * GI_WSTR;

    const int tid = threadIdx.x;
    const int s = blockIdx.x / NG;
    const int g = blockIdx.x % NG;
    const int r0 = g * RPG;
    const int nr = min(RPG, BB - r0);

    for (int u = tid; u < 128 * 128; u += 256) {
        int c = u >> 7, k = u & 127;
        Ws[c * GI_WSTR + k] = Wih[(long)(s * 128 + c) * 129 + k];
    }
    __syncthreads();

    const int rg = tid >> 5, cg = tid & 31;
    float bv[4];
#pragma unroll
    for (int m = 0; m < 4; m++) bv[m] = bih[s * 128 + cg + 32 * m];

    const int nchunk = (nr + 63) >> 6;
    for (int ch = 0; ch < nchunk; ++ch) {
        int rbase = ch * 64;
        for (int u = tid; u < 64 * 32; u += 256) {
            int r = u >> 5, q = u & 31;
            float4 v = make_float4(0.f, 0.f, 0.f, 0.f);
            if (rbase + r < nr)
                v = *(const float4*)(g_ctx + (long)(r0 + rbase + r) * 128 + q * 4);
            *(float4*)(hs + r * 128 + q * 4) = v;
        }
        __syncthreads();

        u64 acc[8][4];
#pragma unroll
        for (int i = 0; i < 8; i++)
#pragma unroll
            for (int m = 0; m < 4; m++) acc[i][m] = 0ULL;

#pragma unroll 2
        for (int kq = 0; kq < 32; ++kq) {
            ulonglong2 w[4];
#pragma unroll
            for (int m = 0; m < 4; m++)
                w[m] = *(const ulonglong2*)(Ws + (cg + 32 * m) * GI_WSTR + kq * 4);
#pragma unroll
            for (int i = 0; i < 8; i++) {
                ulonglong2 hv = *(const ulonglong2*)(hs + (rg * 8 + i) * 128 + kq * 4);
#pragma unroll
                for (int m = 0; m < 4; m++) {
                    ffma2(hv.x, w[m].x, acc[i][m]);
                    ffma2(hv.y, w[m].y, acc[i][m]);
                }
            }
        }
#pragma unroll
        for (int i = 0; i < 8; i++) {
            int row = rbase + rg * 8 + i;
            if (row < nr) {
#pragma unroll
                for (int m = 0; m < 4; m++)
                    g_gi0[(long)(r0 + row) * 768 + s * 128 + cg + 32 * m] =
                        f2sum(acc[i][m]) + bv[m];
            }
        }
        __syncthreads();
    }
}

// per-step recurrent GEMM: gates = h @ Whh^T  (K = 256)
// 512 threads (4 warps/SMSP for latency cover), tile 8 rows x 2 cols/thread.
#define A_WSTR 260
#define A_SMEM_BYTES ((128 * A_WSTR + 64 * 256) * 4)

__global__ void __launch_bounds__(512, 1)
dec_gemm_kernel(const float* __restrict__ Whh)
{
    extern __shared__ float sm[];
    float* Ws = sm;                    // 128 cols x A_WSTR
    float* hs = sm + 128 * A_WSTR;     // 64 rows x 256

    const int tid = threadIdx.x;
    const int s = blockIdx.x / NG;
    const int g = blockIdx.x % NG;
    const int r0 = g * RPG;
    const int nr = min(RPG, BB - r0);

    for (int u = tid; u < 128 * 64; u += 512) {
        int c = u >> 6, q = u & 63;
        *(float4*)(Ws + c * A_WSTR + q * 4) =
            *(const float4*)(Whh + (long)(s * 128 + c) * 256 + q * 4);
    }
    __syncthreads();

    const int rg = tid >> 6;           // 0..7 (warp-uniform -> hs broadcast)
    const int cg = tid & 63;           // 0..63
    const int c0 = cg, c1 = cg + 64;
    const float* w0p = Ws + c0 * A_WSTR;
    const float* w1p = Ws + c1 * A_WSTR;

    const int nchunk = (nr + 63) >> 6;
    for (int ch = 0; ch < nchunk; ++ch) {
        int rbase = ch * 64;
        for (int u = tid; u < 64 * 64; u += 512) {
            int r = u >> 6, q = u & 63;
            float4 v = make_float4(0.f, 0.f, 0.f, 0.f);
            if (rbase + r < nr)
                v = *(const float4*)(g_h + (long)(r0 + rbase + r) * 256 + q * 4);
            *(float4*)(hs + r * 256 + q * 4) = v;
        }
        __syncthreads();

        u64 acc[8][2];
#pragma unroll
        for (int i = 0; i < 8; i++) {
            acc[i][0] = 0ULL;
            acc[i][1] = 0ULL;
        }

#pragma unroll 4
        for (int kq = 0; kq < 64; ++kq) {
            ulonglong2 w0 = *(const ulonglong2*)(w0p + kq * 4);
            ulonglong2 w1 = *(const ulonglong2*)(w1p + kq * 4);
#pragma unroll
            for (int i = 0; i < 8; i++) {
                ulonglong2 hv = *(const ulonglong2*)(hs + (rg * 8 + i) * 256 + kq * 4);
                ffma2(hv.x, w0.x, acc[i][0]);
                ffma2(hv.y, w0.y, acc[i][0]);
                ffma2(hv.x, w1.x, acc[i][1]);
                ffma2(hv.y, w1.y, acc[i][1]);
            }
        }
#pragma unroll
        for (int i = 0; i < 8; i++) {
            int row = rbase + rg * 8 + i;
            if (row < nr) {
                g_gates[(long)(r0 + row) * 768 + s * 128 + c0] = f2sum(acc[i][0]);
                g_gates[(long)(r0 + row) * 768 + s * 128 + c1] = f2sum(acc[i][1]);
            }
        }
        __syncthreads();
    }
}

// ---------------------------------------------------------------------------
// pointwise: gate fusion + h update + linear head.
// ---------------------------------------------------------------------------
__global__ void __launch_bounds__(256, 1)
dec_point_kernel(const float* __restrict__ y, const float* __restrict__ Wih,
                 const float* __restrict__ bhh, const float* __restrict__ linW,
                 const float* __restrict__ linb, float* __restrict__ out, int t)
{
    __shared__ float hs[32 * 256];
    __shared__ float ys[32];
    __shared__ float lw[1024];
    __shared__ float lb[4];

    const int tid = threadIdx.x;
    const int b0 = blockIdx.x * 32;

    if (tid < 32) ys[tid] = y[(long)(b0 + tid) * SS + t];
    for (int u = tid; u < 1024; u += 256) lw[u] = linW[u];
    if (tid < 4) lb[tid] = linb[tid];

    const int c = tid;
    const float wyr = Wih[(long)c * 129 + 128];
    const float wyz = Wih[(long)(c + 256) * 129 + 128];
    const float wyn = Wih[(long)(c + 512) * 129 + 128];
    const float br = bhh[c], bz = bhh[c + 256], bn = bhh[c + 512];
    __syncthreads();

#pragma unroll 4
    for (int r = 0; r < 32; ++r) {
        long b = b0 + r;
        float yv = ys[r];
        float gr  = g_gi0[b * 768 + c]       + yv * wyr + g_gates[b * 768 + c]       + br;
        float gz  = g_gi0[b * 768 + c + 256] + yv * wyz + g_gates[b * 768 + c + 256] + bz;
        float gni = g_gi0[b * 768 + c + 512] + yv * wyn;
        float gnh = g_gates[b * 768 + c + 512] + bn;
        float rr = sigf(gr);
        float zz = sigf(gz);
        float nn = tanhfast(gni + rr * gnh);
        float h  = g_h[b * 256 + c];
        float hn = (1.f - zz) * nn + zz * h;
        g_h[b * 256 + c] = hn;
        hs[r * 256 + c] = hn;
    }
    __syncthreads();

    if (tid < 128) {
        int r = tid >> 2, o = tid & 3;
        float s = lb[o];
#pragma unroll 4
        for (int q = 0; q < 64; ++q) {
            float4 hv = *(float4*)(hs + r * 256 + q * 4);
            float4 wv = *(float4*)(lw + o * 256 + q * 4);
            s += hv.x * wv.x + hv.y * wv.y + hv.z * wv.z + hv.w * wv.w;
        }
        out[(long)(b0 + r) * (SS * 4) + t * 4 + o] = s;
    }
}

extern "C" void kernel_launch(void* const* d_in, const int* in_sizes, int n_in,
                              void* d_out, int out_size) {
    const float* x    = (const float*)d_in[0];
    const float* y    = (const float*)d_in[1];
    const float* eWih = (const float*)d_in[2];
    const float* eWhh = (const float*)d_in[3];
    const float* ebih = (const float*)d_in[4];
    const float* ebhh = (const float*)d_in[5];
    const float* dWih = (const float*)d_in[6];
    const float* dWhh = (const float*)d_in[7];
    const float* dbih = (const float*)d_in[8];
    const float* dbhh = (const float*)d_in[9];
    const float* lW   = (const float*)d_in[10];
    const float* lb   = (const float*)d_in[11];
    float* out = (float*)d_out;

    cudaFuncSetAttribute(enc_kernel, cudaFuncAttributeMaxDynamicSharedMemorySize,
                         E_SMEM_BYTES);
    cudaFuncSetAttribute(dec_gi0_kernel, cudaFuncAttributeMaxDynamicSharedMemorySize,
                         GI_SMEM_BYTES);
    cudaFuncSetAttribute(dec_gemm_kernel, cudaFuncAttributeMaxDynamicSharedMemorySize,
                         A_SMEM_BYTES);

    init_kernel<<<(BB * 118 + 255) / 256, 256>>>(out);
    enc_kernel<<<(BB + E_RPB - 1) / E_RPB, 256, E_SMEM_BYTES>>>(x, eWih, eWhh, ebih, ebhh);
    dec_gi0_kernel<<<6 * NG, 256, GI_SMEM_BYTES>>>(dWih, dbih);
    for (int t = 0; t < NDEC; ++t) {
        dec_gemm_kernel<<<6 * NG, 512, A_SMEM_BYTES>>>(dWhh);
        dec_point_kernel<<<BB / 32, 256>>>(y, dWih, dbhh, lW, lb, out, t);
    }
}

// round 10
// speedup vs baseline: 1.5260x; 1.1176x over previous
#include <cuda_runtime.h>
#include <cuda_bf16.h>
#include <cstdint>

#define BB 4096
#define SS 128
#define EH 128
#define DH 256
#define NDEC 10

typedef unsigned long long u64;

__device__ float g_ctx[BB * EH];
__device__ float g_gates[BB * 768];
__device__ float g_gi0[BB * 768];
__device__ float g_h[BB * DH];
__device__ __nv_bfloat16 g_hb_hi[BB * DH];
__device__ __nv_bfloat16 g_hb_lo[BB * DH];
__device__ __nv_bfloat16 g_wb_hi[768 * DH];
__device__ __nv_bfloat16 g_wb_lo[768 * DH];

__device__ __forceinline__ void ffma2(u64 a, u64 b, u64& c) {
    asm("fma.rn.f32x2 %0, %1, %2, %0;" : "+l"(c) : "l"(a), "l"(b));
}
__device__ __forceinline__ float f2sum(u64 a) {
    float lo = __int_as_float((unsigned)(a & 0xffffffffULL));
    float hi = __int_as_float((unsigned)(a >> 32));
    return lo + hi;
}
__device__ __forceinline__ float sigf(float v) {
    return __fdividef(1.f, 1.f + __expf(-v));
}
__device__ __forceinline__ float tanhfast(float v) {
    float e = __expf(2.f * v);
    return 1.f - __fdividef(2.f, e + 1.f);
}
__device__ __forceinline__ unsigned smem_u32(const void* p) {
    return (unsigned)__cvta_generic_to_shared(p);
}

// ---------------------------------------------------------------------------
// Encoder: R8 baseline (147 blocks x 256 thr, 28 rows/block) — unchanged.
// ---------------------------------------------------------------------------
#define E_RPB 28
#define E_WSTR 132
#define E_SMEM_FLOATS (384 * E_WSTR + E_RPB * 128 + 384 * 5 + 384 + 384 + E_RPB * 5)
#define E_SMEM_BYTES (E_SMEM_FLOATS * 4)

__global__ void __launch_bounds__(256, 1)
enc_kernel(const float* __restrict__ x, const float* __restrict__ Wih,
           const float* __restrict__ Whh, const float* __restrict__ bih,
           const float* __restrict__ bhh)
{
    extern __shared__ float sm[];
    float* Whh_s = sm;
    float* h_s   = Whh_s + 384 * E_WSTR;
    float* Wih_s = h_s + E_RPB * 128;
    float* bih_s = Wih_s + 384 * 5;
    float* bhh_s = bih_s + 384;
    float* x_s   = bhh_s + 384;

    const int tid = threadIdx.x;
    const int b0 = blockIdx.x * E_RPB;

    for (int u = tid; u < 384 * 32; u += 256) {
        int c = u >> 5, q = u & 31;
        *(float4*)(Whh_s + c * E_WSTR + q * 4) =
            *(const float4*)(Whh + c * 128 + q * 4);
    }
    for (int u = tid; u < 384 * 5; u += 256) Wih_s[u] = Wih[u];
    for (int u = tid; u < 384; u += 256) {
        bih_s[u] = bih[u];
        bhh_s[u] = bhh[u];
    }
    for (int u = tid; u < E_RPB * 128; u += 256) h_s[u] = 0.f;
    if (tid < E_RPB * 5) {
        int b = b0 + tid / 5;
        x_s[tid] = (b < BB) ? x[(long)b * (SS * 5) + (tid % 5)] : 0.f;
    }
    __syncthreads();

    const int rg = tid >> 6;
    const int cg = tid & 63;
    const int r0 = rg * 7;
    int col[6];
#pragma unroll
    for (int m = 0; m < 6; m++) col[m] = cg + m * 64;
    const float* wp[6];
#pragma unroll
    for (int m = 0; m < 6; m++) wp[m] = Whh_s + col[m] * E_WSTR;

    for (int t = 0; t < SS; ++t) {
        u64 acc[7][6];
#pragma unroll
        for (int i = 0; i < 7; i++)
#pragma unroll
            for (int m = 0; m < 6; m++) acc[i][m] = 0ULL;

#pragma unroll 2
        for (int kq = 0; kq < 32; ++kq) {
            ulonglong2 w2[6];
#pragma unroll
            for (int m = 0; m < 6; m++)
                w2[m] = *(const ulonglong2*)(wp[m] + kq * 4);
#pragma unroll
            for (int i = 0; i < 7; i++) {
                ulonglong2 hv = *(const ulonglong2*)(h_s + (r0 + i) * 128 + kq * 4);
#pragma unroll
                for (int m = 0; m < 6; m++) {
                    ffma2(hv.x, w2[m].x, acc[i][m]);
                    ffma2(hv.y, w2[m].y, acc[i][m]);
                }
            }
        }

        float hnew[7][2];
#pragma unroll
        for (int i = 0; i < 7; i++) {
            float xv[5];
#pragma unroll
            for (int j = 0; j < 5; j++) xv[j] = x_s[(r0 + i) * 5 + j];
#pragma unroll
            for (int cc = 0; cc < 2; ++cc) {
                int cr = col[cc], cz = col[cc + 2], cn = col[cc + 4];
                float gir = bih_s[cr], giz = bih_s[cz], gin = bih_s[cn];
#pragma unroll
                for (int j = 0; j < 5; j++) {
                    gir += xv[j] * Wih_s[cr * 5 + j];
                    giz += xv[j] * Wih_s[cz * 5 + j];
                    gin += xv[j] * Wih_s[cn * 5 + j];
                }
                float ghr = f2sum(acc[i][cc])     + bhh_s[cr];
                float ghz = f2sum(acc[i][cc + 2]) + bhh_s[cz];
                float ghn = f2sum(acc[i][cc + 4]) + bhh_s[cn];
                float rr = sigf(gir + ghr);
                float zz = sigf(giz + ghz);
                float nn = tanhfast(gin + rr * ghn);
                float hold = h_s[(r0 + i) * 128 + col[cc]];
                hnew[i][cc] = (1.f - zz) * nn + zz * hold;
            }
        }
        __syncthreads();
#pragma unroll
        for (int i = 0; i < 7; i++) {
            h_s[(r0 + i) * 128 + col[0]] = hnew[i][0];
            h_s[(r0 + i) * 128 + col[1]] = hnew[i][1];
        }
        if (t + 1 < SS && tid < E_RPB * 5) {
            int b = b0 + tid / 5;
            x_s[tid] = (b < BB) ? x[(long)b * (SS * 5) + (t + 1) * 5 + (tid % 5)] : 0.f;
        }
        __syncthreads();
    }

    for (int u = tid; u < E_RPB * 32; u += 256) {
        int r = u >> 5, q = u & 31;
        if (b0 + r < BB)
            *(float4*)(g_ctx + (long)(b0 + r) * 128 + q * 4) =
                *(float4*)(h_s + r * 128 + q * 4);
    }
}

// ---------------------------------------------------------------------------
// init: h=ones (fp32 + bf16 hi/lo), out tail = ones, Whh -> bf16 hi/lo.
// ---------------------------------------------------------------------------
__global__ void init_kernel(const float* __restrict__ Whh, float* __restrict__ out) {
    const float4 one4 = make_float4(1.f, 1.f, 1.f, 1.f);
    int i = blockIdx.x * blockDim.x + threadIdx.x;
    if (i < BB * DH / 4) ((float4*)g_h)[i] = one4;
    if (i < BB * DH) {
        g_hb_hi[i] = __float2bfloat16(1.f);
        g_hb_lo[i] = __float2bfloat16(0.f);
    }
    if (i < 768 * DH) {
        float w = Whh[i];
        __nv_bfloat16 hi = __float2bfloat16(w);
        g_wb_hi[i] = hi;
        g_wb_lo[i] = __float2bfloat16(w - __bfloat162float(hi));
    }
    if (i < BB * 118) {
        int b = i / 118, tt = i % 118 + NDEC;
        *(float4*)(out + (long)b * (SS * 4) + tt * 4) = one4;
    }
}

// ---------------------------------------------------------------------------
// gi0 (once): gates0 = bih + ctx @ Wih[:, :128]^T  (scalar; runs once)
// ---------------------------------------------------------------------------
#define NG 24
#define RPG 171
#define GI_WSTR 132
#define GI_SMEM_BYTES ((128 * GI_WSTR + 64 * 128) * 4)

__global__ void __launch_bounds__(256, 1)
dec_gi0_kernel(const float* __restrict__ Wih, const float* __restrict__ bih)
{
    extern __shared__ float sm[];
    float* Ws = sm;
    float* hs = sm + 128 * GI_WSTR;

    const int tid = threadIdx.x;
    const int s = blockIdx.x / NG;
    const int g = blockIdx.x % NG;
    const int r0 = g * RPG;
    const int nr = min(RPG, BB - r0);

    for (int u = tid; u < 128 * 128; u += 256) {
        int c = u >> 7, k = u & 127;
        Ws[c * GI_WSTR + k] = Wih[(long)(s * 128 + c) * 129 + k];
    }
    __syncthreads();

    const int rg = tid >> 5, cg = tid & 31;
    float bv[4];
#pragma unroll
    for (int m = 0; m < 4; m++) bv[m] = bih[s * 128 + cg + 32 * m];

    const int nchunk = (nr + 63) >> 6;
    for (int ch = 0; ch < nchunk; ++ch) {
        int rbase = ch * 64;
        for (int u = tid; u < 64 * 32; u += 256) {
            int r = u >> 5, q = u & 31;
            float4 v = make_float4(0.f, 0.f, 0.f, 0.f);
            if (rbase + r < nr)
                v = *(const float4*)(g_ctx + (long)(r0 + rbase + r) * 128 + q * 4);
            *(float4*)(hs + r * 128 + q * 4) = v;
        }
        __syncthreads();

        u64 acc[8][4];
#pragma unroll
        for (int i = 0; i < 8; i++)
#pragma unroll
            for (int m = 0; m < 4; m++) acc[i][m] = 0ULL;

#pragma unroll 2
        for (int kq = 0; kq < 32; ++kq) {
            ulonglong2 w[4];
#pragma unroll
            for (int m = 0; m < 4; m++)
                w[m] = *(const ulonglong2*)(Ws + (cg + 32 * m) * GI_WSTR + kq * 4);
#pragma unroll
            for (int i = 0; i < 8; i++) {
                ulonglong2 hv = *(const ulonglong2*)(hs + (rg * 8 + i) * 128 + kq * 4);
#pragma unroll
                for (int m = 0; m < 4; m++) {
                    ffma2(hv.x, w[m].x, acc[i][m]);
                    ffma2(hv.y, w[m].y, acc[i][m]);
                }
            }
        }
#pragma unroll
        for (int i = 0; i < 8; i++) {
            int row = rbase + rg * 8 + i;
            if (row < nr) {
#pragma unroll
                for (int m = 0; m < 4; m++)
                    g_gi0[(long)(r0 + row) * 768 + s * 128 + cg + 32 * m] =
                        f2sum(acc[i][m]) + bv[m];
            }
        }
        __syncthreads();
    }
}

// ---------------------------------------------------------------------------
// Tensor-core decoder GEMM via mma.sync (family-generic HMMA; tcgen05 is
// blocked by the harness's plain-sm_103 ptxas target).
// g_gates[4096x768] = h[4096x256] @ Whh^T, split-bf16 3-term fp32 emulation.
// Tile M=128, N=64, K=256. 8 warps; warp tile 64x16 (4 m-frags x 2 n-frags).
// SMEM row stride 264 bf16 (528B): ldmatrix rows hit banks 4r mod 32 ->
// conflict-free. Grid = 32 M-tiles x 12 N-tiles = 384 blocks.
// ---------------------------------------------------------------------------
#define MM_STR 264                      // bf16 elements per padded row
#define MM_A_HI 0
#define MM_A_LO (MM_A_HI + 128 * MM_STR * 2)
#define MM_B_HI (MM_A_LO + 128 * MM_STR * 2)
#define MM_B_LO (MM_B_HI + 64 * MM_STR * 2)
#define MM_SMEM_BYTES (MM_B_LO + 64 * MM_STR * 2)

__device__ __forceinline__ void ldsm_x4(uint32_t* r, unsigned addr) {
    asm volatile("ldmatrix.sync.aligned.m8n8.x4.shared.b16 {%0,%1,%2,%3}, [%4];"
                 : "=r"(r[0]), "=r"(r[1]), "=r"(r[2]), "=r"(r[3]) : "r"(addr));
}
__device__ __forceinline__ void ldsm_x2(uint32_t* r, unsigned addr) {
    asm volatile("ldmatrix.sync.aligned.m8n8.x2.shared.b16 {%0,%1}, [%2];"
                 : "=r"(r[0]), "=r"(r[1]) : "r"(addr));
}
__device__ __forceinline__ void mma_bf16(float* c, const uint32_t* a, const uint32_t* b) {
    asm volatile(
        "mma.sync.aligned.m16n8k16.row.col.f32.bf16.bf16.f32 "
        "{%0,%1,%2,%3}, {%4,%5,%6,%7}, {%8,%9}, {%0,%1,%2,%3};"
        : "+f"(c[0]), "+f"(c[1]), "+f"(c[2]), "+f"(c[3])
        : "r"(a[0]), "r"(a[1]), "r"(a[2]), "r"(a[3]), "r"(b[0]), "r"(b[1]));
}

__global__ void __launch_bounds__(256, 1)
dec_gemm_mma_kernel()
{
    extern __shared__ char smem[];
    const unsigned sb = smem_u32(smem);
    const int tid = threadIdx.x;
    const int lane = tid & 31;
    const int wid = tid >> 5;
    const int warp_m = wid & 1;        // 2 warps over M
    const int warp_n = wid >> 1;       // 4 warps over N
    const int mt = blockIdx.x & 31;
    const int nt = blockIdx.x >> 5;
    const int r0 = mt * 128;
    const int n0 = nt * 64;

    // stage A (h rows r0..+127) hi/lo: 128 rows x 32 segs of 16B
    for (int u = tid; u < 128 * 32; u += 256) {
        int row = u >> 5, seg = u & 31;
        unsigned off = (unsigned)(row * (MM_STR * 2) + seg * 16);
        long src = (long)(r0 + row) * 256 + seg * 8;
        *(uint4*)(smem + MM_A_HI + off) = *(const uint4*)(g_hb_hi + src);
        *(uint4*)(smem + MM_A_LO + off) = *(const uint4*)(g_hb_lo + src);
    }
    // stage B (Whh rows n0..+63) hi/lo
    for (int u = tid; u < 64 * 32; u += 256) {
        int row = u >> 5, seg = u & 31;
        unsigned off = (unsigned)(row * (MM_STR * 2) + seg * 16);
        long src = (long)(n0 + row) * 256 + seg * 8;
        *(uint4*)(smem + MM_B_HI + off) = *(const uint4*)(g_wb_hi + src);
        *(uint4*)(smem + MM_B_LO + off) = *(const uint4*)(g_wb_lo + src);
    }
    __syncthreads();

    float c[4][2][4];
#pragma unroll
    for (int mf = 0; mf < 4; mf++)
#pragma unroll
        for (int nf = 0; nf < 2; nf++)
#pragma unroll
            for (int q = 0; q < 4; q++) c[mf][nf][q] = 0.f;

    // per-lane ldmatrix base offsets
    const unsigned a_row = (unsigned)(warp_m * 64 + (lane & 15));
    const unsigned a_half = (unsigned)((lane >> 4) * 16);
    const unsigned b_row = (unsigned)(warp_n * 16 + (lane & 7));
    const unsigned b_half = (unsigned)(((lane >> 3) & 1) * 16);

#pragma unroll 4
    for (int kk = 0; kk < 16; ++kk) {
        const unsigned koff = (unsigned)(kk * 32);
        uint32_t bh[2][2], bl[2][2];
#pragma unroll
        for (int nf = 0; nf < 2; nf++) {
            unsigned ba = (b_row + nf * 8) * (MM_STR * 2) + koff + b_half;
            ldsm_x2(bh[nf], sb + MM_B_HI + ba);
            ldsm_x2(bl[nf], sb + MM_B_LO + ba);
        }
#pragma unroll
        for (int mf = 0; mf < 4; mf++) {
            unsigned aa = (a_row + mf * 16) * (MM_STR * 2) + koff + a_half;
            uint32_t ah[4], al[4];
            ldsm_x4(ah, sb + MM_A_HI + aa);
            ldsm_x4(al, sb + MM_A_LO + aa);
#pragma unroll
            for (int nf = 0; nf < 2; nf++) {
                mma_bf16(c[mf][nf], ah, bh[nf]);
                mma_bf16(c[mf][nf], ah, bl[nf]);
                mma_bf16(c[mf][nf], al, bh[nf]);
            }
        }
    }

    // write C frags to g_gates
#pragma unroll
    for (int mf = 0; mf < 4; mf++) {
#pragma unroll
        for (int nf = 0; nf < 2; nf++) {
            int row = r0 + warp_m * 64 + mf * 16 + (lane >> 2);
            int col = n0 + warp_n * 16 + nf * 8 + (lane & 3) * 2;
            *(float2*)(g_gates + (long)row * 768 + col) =
                make_float2(c[mf][nf][0], c[mf][nf][1]);
            *(float2*)(g_gates + (long)(row + 8) * 768 + col) =
                make_float2(c[mf][nf][2], c[mf][nf][3]);
        }
    }
}

// ---------------------------------------------------------------------------
// pointwise: gate fusion + h update (fp32 + bf16 hi/lo) + linear head.
// ---------------------------------------------------------------------------
__global__ void __launch_bounds__(256, 1)
dec_point_kernel(const float* __restrict__ y, const float* __restrict__ Wih,
                 const float* __restrict__ bhh, const float* __restrict__ linW,
                 const float* __restrict__ linb, float* __restrict__ out, int t)
{
    __shared__ float hs[32 * 256];
    __shared__ float ys[32];
    __shared__ float lw[1024];
    __shared__ float lb[4];

    const int tid = threadIdx.x;
    const int b0 = blockIdx.x * 32;

    if (tid < 32) ys[tid] = y[(long)(b0 + tid) * SS + t];
    for (int u = tid; u < 1024; u += 256) lw[u] = linW[u];
    if (tid < 4) lb[tid] = linb[tid];

    const int c = tid;
    const float wyr = Wih[(long)c * 129 + 128];
    const float wyz = Wih[(long)(c + 256) * 129 + 128];
    const float wyn = Wih[(long)(c + 512) * 129 + 128];
    const float br = bhh[c], bz = bhh[c + 256], bn = bhh[c + 512];
    __syncthreads();

#pragma unroll 4
    for (int r = 0; r < 32; ++r) {
        long b = b0 + r;
        float yv = ys[r];
        float gr  = g_gi0[b * 768 + c]       + yv * wyr + g_gates[b * 768 + c]       + br;
        float gz  = g_gi0[b * 768 + c + 256] + yv * wyz + g_gates[b * 768 + c + 256] + bz;
        float gni = g_gi0[b * 768 + c + 512] + yv * wyn;
        float gnh = g_gates[b * 768 + c + 512] + bn;
        float rr = sigf(gr);
        float zz = sigf(gz);
        float nn = tanhfast(gni + rr * gnh);
        float h  = g_h[b * 256 + c];
        float hn = (1.f - zz) * nn + zz * h;
        g_h[b * 256 + c] = hn;
        __nv_bfloat16 hi = __float2bfloat16(hn);
        g_hb_hi[b * 256 + c] = hi;
        g_hb_lo[b * 256 + c] = __float2bfloat16(hn - __bfloat162float(hi));
        hs[r * 256 + c] = hn;
    }
    __syncthreads();

    if (tid < 128) {
        int r = tid >> 2, o = tid & 3;
        float s = lb[o];
#pragma unroll 4
        for (int q = 0; q < 64; ++q) {
            float4 hv = *(float4*)(hs + r * 256 + q * 4);
            float4 wv = *(float4*)(lw + o * 256 + q * 4);
            s += hv.x * wv.x + hv.y * wv.y + hv.z * wv.z + hv.w * wv.w;
        }
        out[(long)(b0 + r) * (SS * 4) + t * 4 + o] = s;
    }
}

extern "C" void kernel_launch(void* const* d_in, const int* in_sizes, int n_in,
                              void* d_out, int out_size) {
    const float* x    = (const float*)d_in[0];
    const float* y    = (const float*)d_in[1];
    const float* eWih = (const float*)d_in[2];
    const float* eWhh = (const float*)d_in[3];
    const float* ebih = (const float*)d_in[4];
    const float* ebhh = (const float*)d_in[5];
    const float* dWih = (const float*)d_in[6];
    const float* dWhh = (const float*)d_in[7];
    const float* dbih = (const float*)d_in[8];
    const float* dbhh = (const float*)d_in[9];
    const float* lW   = (const float*)d_in[10];
    const float* lb   = (const float*)d_in[11];
    float* out = (float*)d_out;

    cudaFuncSetAttribute(enc_kernel, cudaFuncAttributeMaxDynamicSharedMemorySize,
                         E_SMEM_BYTES);
    cudaFuncSetAttribute(dec_gi0_kernel, cudaFuncAttributeMaxDynamicSharedMemorySize,
                         GI_SMEM_BYTES);
    cudaFuncSetAttribute(dec_gemm_mma_kernel, cudaFuncAttributeMaxDynamicSharedMemorySize,
                         MM_SMEM_BYTES);

    init_kernel<<<BB, 256>>>(dWhh, out);
    enc_kernel<<<(BB + E_RPB - 1) / E_RPB, 256, E_SMEM_BYTES>>>(x, eWih, eWhh, ebih, ebhh);
    dec_gi0_kernel<<<6 * NG, 256, GI_SMEM_BYTES>>>(dWih, dbih);
    for (int t = 0; t < NDEC; ++t) {
        dec_gemm_mma_kernel<<<384, 256, MM_SMEM_BYTES>>>();
        dec_point_kernel<<<BB / 32, 256>>>(y, dWih, dbhh, lW, lb, out, t);
    }
}

// round 11
// speedup vs baseline: 2.4021x; 1.5741x over previous
#include <cuda_runtime.h>
#include <cuda_bf16.h>
#include <cstdint>

#define BB 4096
#define SS 128
#define EH 128
#define DH 256
#define NDEC 10

typedef unsigned long long u64;

__device__ float g_ctx[BB * EH];
__device__ float g_gates[BB * 768];
__device__ float g_gi0[BB * 768];
__device__ float g_h[BB * DH];
__device__ __nv_bfloat16 g_hb_hi[BB * DH];
__device__ __nv_bfloat16 g_hb_lo[BB * DH];
__device__ __nv_bfloat16 g_wb_hi[768 * DH];
__device__ __nv_bfloat16 g_wb_lo[768 * DH];

__device__ __forceinline__ void ffma2(u64 a, u64 b, u64& c) {
    asm("fma.rn.f32x2 %0, %1, %2, %0;" : "+l"(c) : "l"(a), "l"(b));
}
__device__ __forceinline__ float f2sum(u64 a) {
    float lo = __int_as_float((unsigned)(a & 0xffffffffULL));
    float hi = __int_as_float((unsigned)(a >> 32));
    return lo + hi;
}
__device__ __forceinline__ float sigf(float v) {
    return __fdividef(1.f, 1.f + __expf(-v));
}
__device__ __forceinline__ float tanhfast(float v) {
    float e = __expf(2.f * v);
    return 1.f - __fdividef(2.f, e + 1.f);
}
__device__ __forceinline__ unsigned smem_u32(const void* p) {
    return (unsigned)__cvta_generic_to_shared(p);
}
__device__ __forceinline__ void ldsm_x4(uint32_t* r, unsigned addr) {
    asm volatile("ldmatrix.sync.aligned.m8n8.x4.shared.b16 {%0,%1,%2,%3}, [%4];"
                 : "=r"(r[0]), "=r"(r[1]), "=r"(r[2]), "=r"(r[3]) : "r"(addr));
}
__device__ __forceinline__ void ldsm_x2(uint32_t* r, unsigned addr) {
    asm volatile("ldmatrix.sync.aligned.m8n8.x2.shared.b16 {%0,%1}, [%2];"
                 : "=r"(r[0]), "=r"(r[1]) : "r"(addr));
}
__device__ __forceinline__ void mma_bf16(float* c, const uint32_t* a, const uint32_t* b) {
    asm volatile(
        "mma.sync.aligned.m16n8k16.row.col.f32.bf16.bf16.f32 "
        "{%0,%1,%2,%3}, {%4,%5,%6,%7}, {%8,%9}, {%0,%1,%2,%3};"
        : "+f"(c[0]), "+f"(c[1]), "+f"(c[2]), "+f"(c[3])
        : "r"(a[0]), "r"(a[1]), "r"(a[2]), "r"(a[3]), "r"(b[0]), "r"(b[1]));
}
__device__ __forceinline__ uint32_t pack2_bf16(float a, float b) {
    return (uint32_t)__bfloat16_as_ushort(__float2bfloat16_rn(a)) |
           ((uint32_t)__bfloat16_as_ushort(__float2bfloat16_rn(b)) << 16);
}
#define SW128(x) ((x) ^ (((x) >> 3) & 0x70))

// ---------------------------------------------------------------------------
// Encoder (tensor-core): 147 blocks x 256 threads, 28 batch rows (pad to 32).
// Per step: gates[32x384] = h[32x128] @ Whh^T via split-bf16 3-term mma.sync.
// Whh hi/lo SMEM-resident in SW128 64-k slabs (no padding). h carried fp32 in
// C-fragment-layout registers; re-quantized to bf16 hi/lo A-operand each step.
// Warp w owns gate-triple cols w*16..+15 -> gate fusion is register-local.
// ---------------------------------------------------------------------------
#define E_RPB 28
// smem byte offsets
#define EA_HI 0                    // A hi: 2 slabs x 32*128 = 8192
#define EA_LO 8192                 // A lo: 8192
#define EB_HI 16384                // B hi: 2 slabs x 384*128 = 98304
#define EB_LO 114688               // B lo: 98304
#define E_WIH 212992               // Wih fp32 384*5*4 = 7680
#define E_BIAS 220672              // bsr[128], bsz[128], bin[128], bhn[128] fp32
#define E_XS 222720                // x double-buffer 2 x 160 fp32 = 1280
#define E2_SMEM_BYTES 224000

__global__ void __launch_bounds__(256, 1)
enc_tc_kernel(const float* __restrict__ x, const float* __restrict__ Wih,
              const float* __restrict__ Whh, const float* __restrict__ bih,
              const float* __restrict__ bhh)
{
    extern __shared__ char smem[];
    const unsigned sb = smem_u32(smem);
    float* WihS = (float*)(smem + E_WIH);
    float* bias = (float*)(smem + E_BIAS);
    float* xsb  = (float*)(smem + E_XS);

    const int tid = threadIdx.x;
    const int lane = tid & 31;
    const int w = tid >> 5;
    const int b0 = blockIdx.x * E_RPB;

    // zero A hi/lo (16384 B)
    for (int u = tid; u < 4096; u += 256) ((uint32_t*)smem)[u] = 0u;
    // stage Whh -> bf16 hi/lo SW128 slabs
    for (int u = tid; u < 384 * 64; u += 256) {
        int c = u >> 6, kp = u & 63;            // kp = k/2
        float2 v = *(const float2*)(Whh + (long)c * 128 + kp * 2);
        float h0 = __bfloat162float(__float2bfloat16_rn(v.x));
        float h1 = __bfloat162float(__float2bfloat16_rn(v.y));
        int slab = kp >> 5;
        unsigned byte = (unsigned)(c * 128 + (kp & 31) * 4);
        unsigned sw = SW128(byte);
        *(uint32_t*)(smem + EB_HI + slab * 49152 + sw) = pack2_bf16(h0, h1);
        *(uint32_t*)(smem + EB_LO + slab * 49152 + sw) = pack2_bf16(v.x - h0, v.y - h1);
    }
    for (int u = tid; u < 384 * 5; u += 256) WihS[u] = Wih[u];
    if (tid < 128) {
        bias[tid]       = bih[tid] + bhh[tid];              // bsr
        bias[128 + tid] = bih[128 + tid] + bhh[128 + tid];  // bsz
        bias[256 + tid] = bih[256 + tid];                   // bin
        bias[384 + tid] = bhh[256 + tid];                   // bhn
    }
    if (tid < 160) {
        int row = tid / 5, b = b0 + row;
        xsb[tid] = (row < E_RPB && b < BB) ? x[(long)b * (SS * 5) + (tid % 5)] : 0.f;
    }
    __syncthreads();

    // per-lane constants: 4 owned columns (2 n-frags x 2), their biases
    int cl[2][2];
    float c_bsr[2][2], c_bsz[2][2], c_bin[2][2], c_bhn[2][2];
#pragma unroll
    for (int nf = 0; nf < 2; nf++)
#pragma unroll
        for (int j = 0; j < 2; j++) {
            int c = w * 16 + nf * 8 + (lane & 3) * 2 + j;
            cl[nf][j] = c;
            c_bsr[nf][j] = bias[c];
            c_bsz[nf][j] = bias[128 + c];
            c_bin[nf][j] = bias[256 + c];
            c_bhn[nf][j] = bias[384 + c];
        }

    float hold[2][2][2][2];   // [mf][nf][qr][j], fp32 exact h
#pragma unroll
    for (int a = 0; a < 2; a++)
#pragma unroll
        for (int b_ = 0; b_ < 2; b_++)
#pragma unroll
            for (int c = 0; c < 2; c++)
#pragma unroll
                for (int d = 0; d < 2; d++) hold[a][b_][c][d] = 0.f;

    const unsigned a_koff_half = (unsigned)((lane >> 4) * 16);
    const unsigned b_koff_half = (unsigned)(((lane >> 3) & 1) * 16);

    for (int t = 0; t < SS; ++t) {
        float cfr[2][3][2][4];
#pragma unroll
        for (int mf = 0; mf < 2; mf++)
#pragma unroll
            for (int g = 0; g < 3; g++)
#pragma unroll
                for (int nf = 0; nf < 2; nf++)
#pragma unroll
                    for (int q = 0; q < 4; q++) cfr[mf][g][nf][q] = 0.f;

#pragma unroll
        for (int kk = 0; kk < 8; ++kk) {
            const unsigned aslab = (unsigned)((kk >> 2) * 4096);
            const unsigned bslab = (unsigned)((kk >> 2) * 49152);
            const unsigned akoff = (unsigned)((kk & 3) * 32) + a_koff_half;
            const unsigned bkoff = (unsigned)((kk & 3) * 32) + b_koff_half;
            uint32_t ah[2][4], al[2][4];
#pragma unroll
            for (int mf = 0; mf < 2; mf++) {
                unsigned byte = (unsigned)((mf * 16 + (lane & 15)) * 128) + akoff;
                unsigned sw = SW128(byte);
                ldsm_x4(ah[mf], sb + EA_HI + aslab + sw);
                ldsm_x4(al[mf], sb + EA_LO + aslab + sw);
            }
#pragma unroll
            for (int g = 0; g < 3; g++)
#pragma unroll
                for (int nf = 0; nf < 2; nf++) {
                    unsigned byte =
                        (unsigned)((g * 128 + w * 16 + nf * 8 + (lane & 7)) * 128) + bkoff;
                    unsigned sw = SW128(byte);
                    uint32_t bh[2], bl[2];
                    ldsm_x2(bh, sb + EB_HI + bslab + sw);
                    ldsm_x2(bl, sb + EB_LO + bslab + sw);
#pragma unroll
                    for (int mf = 0; mf < 2; mf++) {
                        mma_bf16(cfr[mf][g][nf], ah[mf], bh);
                        mma_bf16(cfr[mf][g][nf], ah[mf], bl);
                        mma_bf16(cfr[mf][g][nf], al[mf], bh);
                    }
                }
        }

        // epilogue: gates + h update, all register-local
        const float* xs = xsb + (t & 1) * 160;
#pragma unroll
        for (int mf = 0; mf < 2; mf++) {
#pragma unroll
            for (int qr = 0; qr < 2; qr++) {
                int row = mf * 16 + (lane >> 2) + qr * 8;
                float xv[5];
#pragma unroll
                for (int j = 0; j < 5; j++) xv[j] = xs[row * 5 + j];
#pragma unroll
                for (int nf = 0; nf < 2; nf++)
#pragma unroll
                    for (int j = 0; j < 2; j++) {
                        int c = cl[nf][j];
                        int q = qr * 2 + j;
                        float gr = cfr[mf][0][nf][q] + c_bsr[nf][j];
                        float gz = cfr[mf][1][nf][q] + c_bsz[nf][j];
                        float ghn = cfr[mf][2][nf][q] + c_bhn[nf][j];
                        float gn = c_bin[nf][j];
#pragma unroll
                        for (int jj = 0; jj < 5; jj++) {
                            gr += xv[jj] * WihS[c * 5 + jj];
                            gz += xv[jj] * WihS[(c + 128) * 5 + jj];
                            gn += xv[jj] * WihS[(c + 256) * 5 + jj];
                        }
                        float rr = sigf(gr);
                        float zz = sigf(gz);
                        float nn = tanhfast(gn + rr * ghn);
                        hold[mf][nf][qr][j] =
                            (1.f - zz) * nn + zz * hold[mf][nf][qr][j];
                    }
            }
        }

        if (t + 1 < SS && tid < 160) {
            int row = tid / 5, b = b0 + row;
            xsb[((t + 1) & 1) * 160 + tid] =
                (row < E_RPB && b < BB) ? x[(long)b * (SS * 5) + (t + 1) * 5 + (tid % 5)]
                                        : 0.f;
        }
        __syncthreads();   // all A-frag reads of h done

        // write h_new as bf16 hi/lo into A operand (SW128 slabs)
#pragma unroll
        for (int mf = 0; mf < 2; mf++)
#pragma unroll
            for (int qr = 0; qr < 2; qr++)
#pragma unroll
                for (int nf = 0; nf < 2; nf++) {
                    int row = mf * 16 + (lane >> 2) + qr * 8;
                    int c0 = cl[nf][0];
                    float h0 = hold[mf][nf][qr][0], h1 = hold[mf][nf][qr][1];
                    float h0h = __bfloat162float(__float2bfloat16_rn(h0));
                    float h1h = __bfloat162float(__float2bfloat16_rn(h1));
                    int slab = c0 >> 6;
                    unsigned byte = (unsigned)(row * 128 + (c0 & 63) * 2);
                    unsigned sw = SW128(byte);
                    *(uint32_t*)(smem + EA_HI + slab * 4096 + sw) = pack2_bf16(h0h, h1h);
                    *(uint32_t*)(smem + EA_LO + slab * 4096 + sw) =
                        pack2_bf16(h0 - h0h, h1 - h1h);
                }
        __syncthreads();   // h visible for next step
    }

    // write ctx from fp32 registers
#pragma unroll
    for (int mf = 0; mf < 2; mf++)
#pragma unroll
        for (int qr = 0; qr < 2; qr++) {
            int row = mf * 16 + (lane >> 2) + qr * 8;
            if (row < E_RPB && b0 + row < BB) {
#pragma unroll
                for (int nf = 0; nf < 2; nf++) {
                    *(float2*)(g_ctx + (long)(b0 + row) * 128 + cl[nf][0]) =
                        make_float2(hold[mf][nf][qr][0], hold[mf][nf][qr][1]);
                }
            }
        }
}

// ---------------------------------------------------------------------------
// init: h=ones (fp32 + bf16 hi/lo), out tail = ones, dec Whh -> bf16 hi/lo.
// ---------------------------------------------------------------------------
__global__ void init_kernel(const float* __restrict__ Whh, float* __restrict__ out) {
    const float4 one4 = make_float4(1.f, 1.f, 1.f, 1.f);
    int i = blockIdx.x * blockDim.x + threadIdx.x;
    if (i < BB * DH / 4) ((float4*)g_h)[i] = one4;
    if (i < BB * DH) {
        g_hb_hi[i] = __float2bfloat16(1.f);
        g_hb_lo[i] = __float2bfloat16(0.f);
    }
    if (i < 768 * DH) {
        float w = Whh[i];
        __nv_bfloat16 hi = __float2bfloat16(w);
        g_wb_hi[i] = hi;
        g_wb_lo[i] = __float2bfloat16(w - __bfloat162float(hi));
    }
    if (i < BB * 118) {
        int b = i / 118, tt = i % 118 + NDEC;
        *(float4*)(out + (long)b * (SS * 4) + tt * 4) = one4;
    }
}

// ---------------------------------------------------------------------------
// gi0 (once): gates0 = bih + ctx @ Wih[:, :128]^T  (scalar; runs once)
// ---------------------------------------------------------------------------
#define NG 24
#define RPG 171
#define GI_WSTR 132
#define GI_SMEM_BYTES ((128 * GI_WSTR + 64 * 128) * 4)

__global__ void __launch_bounds__(256, 1)
dec_gi0_kernel(const float* __restrict__ Wih, const float* __restrict__ bih)
{
    extern __shared__ float sm[];
    float* Ws = sm;
    float* hs = sm + 128 * GI_WSTR;

    const int tid = threadIdx.x;
    const int s = blockIdx.x / NG;
    const int g = blockIdx.x % NG;
    const int r0 = g * RPG;
    const int nr = min(RPG, BB - r0);

    for (int u = tid; u < 128 * 128; u += 256) {
        int c = u >> 7, k = u & 127;
        Ws[c * GI_WSTR + k] = Wih[(long)(s * 128 + c) * 129 + k];
    }
    __syncthreads();

    const int rg = tid >> 5, cg = tid & 31;
    float bv[4];
#pragma unroll
    for (int m = 0; m < 4; m++) bv[m] = bih[s * 128 + cg + 32 * m];

    const int nchunk = (nr + 63) >> 6;
    for (int ch = 0; ch < nchunk; ++ch) {
        int rbase = ch * 64;
        for (int u = tid; u < 64 * 32; u += 256) {
            int r = u >> 5, q = u & 31;
            float4 v = make_float4(0.f, 0.f, 0.f, 0.f);
            if (rbase + r < nr)
                v = *(const float4*)(g_ctx + (long)(r0 + rbase + r) * 128 + q * 4);
            *(float4*)(hs + r * 128 + q * 4) = v;
        }
        __syncthreads();

        u64 acc[8][4];
#pragma unroll
        for (int i = 0; i < 8; i++)
#pragma unroll
            for (int m = 0; m < 4; m++) acc[i][m] = 0ULL;

#pragma unroll 2
        for (int kq = 0; kq < 32; ++kq) {
            ulonglong2 w[4];
#pragma unroll
            for (int m = 0; m < 4; m++)
                w[m] = *(const ulonglong2*)(Ws + (cg + 32 * m) * GI_WSTR + kq * 4);
#pragma unroll
            for (int i = 0; i < 8; i++) {
                ulonglong2 hv = *(const ulonglong2*)(hs + (rg * 8 + i) * 128 + kq * 4);
#pragma unroll
                for (int m = 0; m < 4; m++) {
                    ffma2(hv.x, w[m].x, acc[i][m]);
                    ffma2(hv.y, w[m].y, acc[i][m]);
                }
            }
        }
#pragma unroll
        for (int i = 0; i < 8; i++) {
            int row = rbase + rg * 8 + i;
            if (row < nr) {
#pragma unroll
                for (int m = 0; m < 4; m++)
                    g_gi0[(long)(r0 + row) * 768 + s * 128 + cg + 32 * m] =
                        f2sum(acc[i][m]) + bv[m];
            }
        }
        __syncthreads();
    }
}

// ---------------------------------------------------------------------------
// Decoder GEMM via mma.sync (R10, unchanged): tile M=128 N=64 K=256.
// ---------------------------------------------------------------------------
#define MM_STR 264
#define MM_A_HI 0
#define MM_A_LO (MM_A_HI + 128 * MM_STR * 2)
#define MM_B_HI (MM_A_LO + 128 * MM_STR * 2)
#define MM_B_LO (MM_B_HI + 64 * MM_STR * 2)
#define MM_SMEM_BYTES (MM_B_LO + 64 * MM_STR * 2)

__global__ void __launch_bounds__(256, 1)
dec_gemm_mma_kernel()
{
    extern __shared__ char smem[];
    const unsigned sb = smem_u32(smem);
    const int tid = threadIdx.x;
    const int lane = tid & 31;
    const int wid = tid >> 5;
    const int warp_m = wid & 1;
    const int warp_n = wid >> 1;
    const int mt = blockIdx.x & 31;
    const int nt = blockIdx.x >> 5;
    const int r0 = mt * 128;
    const int n0 = nt * 64;

    for (int u = tid; u < 128 * 32; u += 256) {
        int row = u >> 5, seg = u & 31;
        unsigned off = (unsigned)(row * (MM_STR * 2) + seg * 16);
        long src = (long)(r0 + row) * 256 + seg * 8;
        *(uint4*)(smem + MM_A_HI + off) = *(const uint4*)(g_hb_hi + src);
        *(uint4*)(smem + MM_A_LO + off) = *(const uint4*)(g_hb_lo + src);
    }
    for (int u = tid; u < 64 * 32; u += 256) {
        int row = u >> 5, seg = u & 31;
        unsigned off = (unsigned)(row * (MM_STR * 2) + seg * 16);
        long src = (long)(n0 + row) * 256 + seg * 8;
        *(uint4*)(smem + MM_B_HI + off) = *(const uint4*)(g_wb_hi + src);
        *(uint4*)(smem + MM_B_LO + off) = *(const uint4*)(g_wb_lo + src);
    }
    __syncthreads();

    float c[4][2][4];
#pragma unroll
    for (int mf = 0; mf < 4; mf++)
#pragma unroll
        for (int nf = 0; nf < 2; nf++)
#pragma unroll
            for (int q = 0; q < 4; q++) c[mf][nf][q] = 0.f;

    const unsigned a_row = (unsigned)(warp_m * 64 + (lane & 15));
    const unsigned a_half = (unsigned)((lane >> 4) * 16);
    const unsigned b_row = (unsigned)(warp_n * 16 + (lane & 7));
    const unsigned b_half = (unsigned)(((lane >> 3) & 1) * 16);

#pragma unroll 4
    for (int kk = 0; kk < 16; ++kk) {
        const unsigned koff = (unsigned)(kk * 32);
        uint32_t bh[2][2], bl[2][2];
#pragma unroll
        for (int nf = 0; nf < 2; nf++) {
            unsigned ba = (b_row + nf * 8) * (MM_STR * 2) + koff + b_half;
            ldsm_x2(bh[nf], sb + MM_B_HI + ba);
            ldsm_x2(bl[nf], sb + MM_B_LO + ba);
        }
#pragma unroll
        for (int mf = 0; mf < 4; mf++) {
            unsigned aa = (a_row + mf * 16) * (MM_STR * 2) + koff + a_half;
            uint32_t ah[4], al[4];
            ldsm_x4(ah, sb + MM_A_HI + aa);
            ldsm_x4(al, sb + MM_A_LO + aa);
#pragma unroll
            for (int nf = 0; nf < 2; nf++) {
                mma_bf16(c[mf][nf], ah, bh[nf]);
                mma_bf16(c[mf][nf], ah, bl[nf]);
                mma_bf16(c[mf][nf], al, bh[nf]);
            }
        }
    }

#pragma unroll
    for (int mf = 0; mf < 4; mf++) {
#pragma unroll
        for (int nf = 0; nf < 2; nf++) {
            int row = r0 + warp_m * 64 + mf * 16 + (lane >> 2);
            int col = n0 + warp_n * 16 + nf * 8 + (lane & 3) * 2;
            *(float2*)(g_gates + (long)row * 768 + col) =
                make_float2(c[mf][nf][0], c[mf][nf][1]);
            *(float2*)(g_gates + (long)(row + 8) * 768 + col) =
                make_float2(c[mf][nf][2], c[mf][nf][3]);
        }
    }
}

// ---------------------------------------------------------------------------
// pointwise: gate fusion + h update (fp32 + bf16 hi/lo) + linear head.
// ---------------------------------------------------------------------------
__global__ void __launch_bounds__(256, 1)
dec_point_kernel(const float* __restrict__ y, const float* __restrict__ Wih,
                 const float* __restrict__ bhh, const float* __restrict__ linW,
                 const float* __restrict__ linb, float* __restrict__ out, int t)
{
    __shared__ float hs[32 * 256];
    __shared__ float ys[32];
    __shared__ float lw[1024];
    __shared__ float lb[4];

    const int tid = threadIdx.x;
    const int b0 = blockIdx.x * 32;

    if (tid < 32) ys[tid] = y[(long)(b0 + tid) * SS + t];
    for (int u = tid; u < 1024; u += 256) lw[u] = linW[u];
    if (tid < 4) lb[tid] = linb[tid];

    const int c = tid;
    const float wyr = Wih[(long)c * 129 + 128];
    const float wyz = Wih[(long)(c + 256) * 129 + 128];
    const float wyn = Wih[(long)(c + 512) * 129 + 128];
    const float br = bhh[c], bz = bhh[c + 256], bn = bhh[c + 512];
    __syncthreads();

#pragma unroll 4
    for (int r = 0; r < 32; ++r) {
        long b = b0 + r;
        float yv = ys[r];
        float gr  = g_gi0[b * 768 + c]       + yv * wyr + g_gates[b * 768 + c]       + br;
        float gz  = g_gi0[b * 768 + c + 256] + yv * wyz + g_gates[b * 768 + c + 256] + bz;
        float gni = g_gi0[b * 768 + c + 512] + yv * wyn;
        float gnh = g_gates[b * 768 + c + 512] + bn;
        float rr = sigf(gr);
        float zz = sigf(gz);
        float nn = tanhfast(gni + rr * gnh);
        float h  = g_h[b * 256 + c];
        float hn = (1.f - zz) * nn + zz * h;
        g_h[b * 256 + c] = hn;
        __nv_bfloat16 hi = __float2bfloat16(hn);
        g_hb_hi[b * 256 + c] = hi;
        g_hb_lo[b * 256 + c] = __float2bfloat16(hn - __bfloat162float(hi));
        hs[r * 256 + c] = hn;
    }
    __syncthreads();

    if (tid < 128) {
        int r = tid >> 2, o = tid & 3;
        float s = lb[o];
#pragma unroll 4
        for (int q = 0; q < 64; ++q) {
            float4 hv = *(float4*)(hs + r * 256 + q * 4);
            float4 wv = *(float4*)(lw + o * 256 + q * 4);
            s += hv.x * wv.x + hv.y * wv.y + hv.z * wv.z + hv.w * wv.w;
        }
        out[(long)(b0 + r) * (SS * 4) + t * 4 + o] = s;
    }
}

// pads: put enc_tc_kernel at capture slot #6 (ncu -s 5 -c 1)
__global__ void pad1_kernel() {}
__global__ void pad2_kernel() {}
__global__ void pad3_kernel() {}
__global__ void pad4_kernel() {}

extern "C" void kernel_launch(void* const* d_in, const int* in_sizes, int n_in,
                              void* d_out, int out_size) {
    const float* x    = (const float*)d_in[0];
    const float* y    = (const float*)d_in[1];
    const float* eWih = (const float*)d_in[2];
    const float* eWhh = (const float*)d_in[3];
    const float* ebih = (const float*)d_in[4];
    const float* ebhh = (const float*)d_in[5];
    const float* dWih = (const float*)d_in[6];
    const float* dWhh = (const float*)d_in[7];
    const float* dbih = (const float*)d_in[8];
    const float* dbhh = (const float*)d_in[9];
    const float* lW   = (const float*)d_in[10];
    const float* lb   = (const float*)d_in[11];
    float* out = (float*)d_out;

    cudaFuncSetAttribute(enc_tc_kernel, cudaFuncAttributeMaxDynamicSharedMemorySize,
                         E2_SMEM_BYTES);
    cudaFuncSetAttribute(dec_gi0_kernel, cudaFuncAttributeMaxDynamicSharedMemorySize,
                         GI_SMEM_BYTES);
    cudaFuncSetAttribute(dec_gemm_mma_kernel, cudaFuncAttributeMaxDynamicSharedMemorySize,
                         MM_SMEM_BYTES);

    init_kernel<<<BB, 256>>>(dWhh, out);                          // 1
    pad1_kernel<<<1, 32>>>();                                     // 2
    pad2_kernel<<<1, 32>>>();                                     // 3
    pad3_kernel<<<1, 32>>>();                                     // 4
    pad4_kernel<<<1, 32>>>();                                     // 5
    enc_tc_kernel<<<(BB + E_RPB - 1) / E_RPB, 256, E2_SMEM_BYTES>>>(  // 6 <- ncu
        x, eWih, eWhh, ebih, ebhh);
    dec_gi0_kernel<<<6 * NG, 256, GI_SMEM_BYTES>>>(dWih, dbih);
    for (int t = 0; t < NDEC; ++t) {
        dec_gemm_mma_kernel<<<384, 256, MM_SMEM_BYTES>>>();
        dec_point_kernel<<<BB / 32, 256>>>(y, dWih, dbhh, lW, lb, out, t);
    }
}

// round 12
// speedup vs baseline: 2.5566x; 1.0643x over previous
#include <cuda_runtime.h>
#include <cuda_bf16.h>
#include <cstdint>

#define BB 4096
#define SS 128
#define EH 128
#define DH 256
#define NDEC 10

typedef unsigned long long u64;

__device__ float g_ctx[BB * EH];
__device__ float g_gates[BB * 768];
__device__ float g_gi0[BB * 768];
__device__ float g_h[BB * DH];
__device__ __nv_bfloat16 g_hb_hi[BB * DH];
__device__ __nv_bfloat16 g_hb_lo[BB * DH];
__device__ __nv_bfloat16 g_wb_hi[768 * DH];
__device__ __nv_bfloat16 g_wb_lo[768 * DH];

__device__ __forceinline__ void ffma2(u64 a, u64 b, u64& c) {
    asm("fma.rn.f32x2 %0, %1, %2, %0;" : "+l"(c) : "l"(a), "l"(b));
}
__device__ __forceinline__ float f2sum(u64 a) {
    float lo = __int_as_float((unsigned)(a & 0xffffffffULL));
    float hi = __int_as_float((unsigned)(a >> 32));
    return lo + hi;
}
__device__ __forceinline__ float sigf(float v) {
    return __fdividef(1.f, 1.f + __expf(-v));
}
__device__ __forceinline__ float tanhfast(float v) {
    float e = __expf(2.f * v);
    return 1.f - __fdividef(2.f, e + 1.f);
}
__device__ __forceinline__ unsigned smem_u32(const void* p) {
    return (unsigned)__cvta_generic_to_shared(p);
}
__device__ __forceinline__ void ldsm_x4(uint32_t* r, unsigned addr) {
    asm volatile("ldmatrix.sync.aligned.m8n8.x4.shared.b16 {%0,%1,%2,%3}, [%4];"
                 : "=r"(r[0]), "=r"(r[1]), "=r"(r[2]), "=r"(r[3]) : "r"(addr));
}
__device__ __forceinline__ void ldsm_x2(uint32_t* r, unsigned addr) {
    asm volatile("ldmatrix.sync.aligned.m8n8.x2.shared.b16 {%0,%1}, [%2];"
                 : "=r"(r[0]), "=r"(r[1]) : "r"(addr));
}
__device__ __forceinline__ void mma_bf16(float* c, const uint32_t* a, const uint32_t* b) {
    asm volatile(
        "mma.sync.aligned.m16n8k16.row.col.f32.bf16.bf16.f32 "
        "{%0,%1,%2,%3}, {%4,%5,%6,%7}, {%8,%9}, {%0,%1,%2,%3};"
        : "+f"(c[0]), "+f"(c[1]), "+f"(c[2]), "+f"(c[3])
        : "r"(a[0]), "r"(a[1]), "r"(a[2]), "r"(a[3]), "r"(b[0]), "r"(b[1]));
}
__device__ __forceinline__ uint32_t pack2_bf16(float a, float b) {
    return (uint32_t)__bfloat16_as_ushort(__float2bfloat16_rn(a)) |
           ((uint32_t)__bfloat16_as_ushort(__float2bfloat16_rn(b)) << 16);
}
#define SW128(x) ((x) ^ (((x) >> 3) & 0x70))

// ---------------------------------------------------------------------------
// Encoder (tensor-core): R11, unchanged. 147 blocks x 256 threads.
// ---------------------------------------------------------------------------
#define E_RPB 28
#define EA_HI 0
#define EA_LO 8192
#define EB_HI 16384
#define EB_LO 114688
#define E_WIH 212992
#define E_BIAS 220672
#define E_XS 222720
#define E2_SMEM_BYTES 224000

__global__ void __launch_bounds__(256, 1)
enc_tc_kernel(const float* __restrict__ x, const float* __restrict__ Wih,
              const float* __restrict__ Whh, const float* __restrict__ bih,
              const float* __restrict__ bhh)
{
    extern __shared__ char smem[];
    const unsigned sb = smem_u32(smem);
    float* WihS = (float*)(smem + E_WIH);
    float* bias = (float*)(smem + E_BIAS);
    float* xsb  = (float*)(smem + E_XS);

    const int tid = threadIdx.x;
    const int lane = tid & 31;
    const int w = tid >> 5;
    const int b0 = blockIdx.x * E_RPB;

    for (int u = tid; u < 4096; u += 256) ((uint32_t*)smem)[u] = 0u;
    for (int u = tid; u < 384 * 64; u += 256) {
        int c = u >> 6, kp = u & 63;
        float2 v = *(const float2*)(Whh + (long)c * 128 + kp * 2);
        float h0 = __bfloat162float(__float2bfloat16_rn(v.x));
        float h1 = __bfloat162float(__float2bfloat16_rn(v.y));
        int slab = kp >> 5;
        unsigned byte = (unsigned)(c * 128 + (kp & 31) * 4);
        unsigned sw = SW128(byte);
        *(uint32_t*)(smem + EB_HI + slab * 49152 + sw) = pack2_bf16(h0, h1);
        *(uint32_t*)(smem + EB_LO + slab * 49152 + sw) = pack2_bf16(v.x - h0, v.y - h1);
    }
    for (int u = tid; u < 384 * 5; u += 256) WihS[u] = Wih[u];
    if (tid < 128) {
        bias[tid]       = bih[tid] + bhh[tid];
        bias[128 + tid] = bih[128 + tid] + bhh[128 + tid];
        bias[256 + tid] = bih[256 + tid];
        bias[384 + tid] = bhh[256 + tid];
    }
    if (tid < 160) {
        int row = tid / 5, b = b0 + row;
        xsb[tid] = (row < E_RPB && b < BB) ? x[(long)b * (SS * 5) + (tid % 5)] : 0.f;
    }
    __syncthreads();

    int cl[2][2];
    float c_bsr[2][2], c_bsz[2][2], c_bin[2][2], c_bhn[2][2];
#pragma unroll
    for (int nf = 0; nf < 2; nf++)
#pragma unroll
        for (int j = 0; j < 2; j++) {
            int c = w * 16 + nf * 8 + (lane & 3) * 2 + j;
            cl[nf][j] = c;
            c_bsr[nf][j] = bias[c];
            c_bsz[nf][j] = bias[128 + c];
            c_bin[nf][j] = bias[256 + c];
            c_bhn[nf][j] = bias[384 + c];
        }

    float hold[2][2][2][2];
#pragma unroll
    for (int a = 0; a < 2; a++)
#pragma unroll
        for (int b_ = 0; b_ < 2; b_++)
#pragma unroll
            for (int c = 0; c < 2; c++)
#pragma unroll
                for (int d = 0; d < 2; d++) hold[a][b_][c][d] = 0.f;

    const unsigned a_koff_half = (unsigned)((lane >> 4) * 16);
    const unsigned b_koff_half = (unsigned)(((lane >> 3) & 1) * 16);

    for (int t = 0; t < SS; ++t) {
        float cfr[2][3][2][4];
#pragma unroll
        for (int mf = 0; mf < 2; mf++)
#pragma unroll
            for (int g = 0; g < 3; g++)
#pragma unroll
                for (int nf = 0; nf < 2; nf++)
#pragma unroll
                    for (int q = 0; q < 4; q++) cfr[mf][g][nf][q] = 0.f;

#pragma unroll
        for (int kk = 0; kk < 8; ++kk) {
            const unsigned aslab = (unsigned)((kk >> 2) * 4096);
            const unsigned bslab = (unsigned)((kk >> 2) * 49152);
            const unsigned akoff = (unsigned)((kk & 3) * 32) + a_koff_half;
            const unsigned bkoff = (unsigned)((kk & 3) * 32) + b_koff_half;
            uint32_t ah[2][4], al[2][4];
#pragma unroll
            for (int mf = 0; mf < 2; mf++) {
                unsigned byte = (unsigned)((mf * 16 + (lane & 15)) * 128) + akoff;
                unsigned sw = SW128(byte);
                ldsm_x4(ah[mf], sb + EA_HI + aslab + sw);
                ldsm_x4(al[mf], sb + EA_LO + aslab + sw);
            }
#pragma unroll
            for (int g = 0; g < 3; g++)
#pragma unroll
                for (int nf = 0; nf < 2; nf++) {
                    unsigned byte =
                        (unsigned)((g * 128 + w * 16 + nf * 8 + (lane & 7)) * 128) + bkoff;
                    unsigned sw = SW128(byte);
                    uint32_t bh[2], bl[2];
                    ldsm_x2(bh, sb + EB_HI + bslab + sw);
                    ldsm_x2(bl, sb + EB_LO + bslab + sw);
#pragma unroll
                    for (int mf = 0; mf < 2; mf++) {
                        mma_bf16(cfr[mf][g][nf], ah[mf], bh);
                        mma_bf16(cfr[mf][g][nf], ah[mf], bl);
                        mma_bf16(cfr[mf][g][nf], al[mf], bh);
                    }
                }
        }

        const float* xs = xsb + (t & 1) * 160;
#pragma unroll
        for (int mf = 0; mf < 2; mf++) {
#pragma unroll
            for (int qr = 0; qr < 2; qr++) {
                int row = mf * 16 + (lane >> 2) + qr * 8;
                float xv[5];
#pragma unroll
                for (int j = 0; j < 5; j++) xv[j] = xs[row * 5 + j];
#pragma unroll
                for (int nf = 0; nf < 2; nf++)
#pragma unroll
                    for (int j = 0; j < 2; j++) {
                        int c = cl[nf][j];
                        int q = qr * 2 + j;
                        float gr = cfr[mf][0][nf][q] + c_bsr[nf][j];
                        float gz = cfr[mf][1][nf][q] + c_bsz[nf][j];
                        float ghn = cfr[mf][2][nf][q] + c_bhn[nf][j];
                        float gn = c_bin[nf][j];
#pragma unroll
                        for (int jj = 0; jj < 5; jj++) {
                            gr += xv[jj] * WihS[c * 5 + jj];
                            gz += xv[jj] * WihS[(c + 128) * 5 + jj];
                            gn += xv[jj] * WihS[(c + 256) * 5 + jj];
                        }
                        float rr = sigf(gr);
                        float zz = sigf(gz);
                        float nn = tanhfast(gn + rr * ghn);
                        hold[mf][nf][qr][j] =
                            (1.f - zz) * nn + zz * hold[mf][nf][qr][j];
                    }
            }
        }

        if (t + 1 < SS && tid < 160) {
            int row = tid / 5, b = b0 + row;
            xsb[((t + 1) & 1) * 160 + tid] =
                (row < E_RPB && b < BB) ? x[(long)b * (SS * 5) + (t + 1) * 5 + (tid % 5)]
                                        : 0.f;
        }
        __syncthreads();

#pragma unroll
        for (int mf = 0; mf < 2; mf++)
#pragma unroll
            for (int qr = 0; qr < 2; qr++)
#pragma unroll
                for (int nf = 0; nf < 2; nf++) {
                    int row = mf * 16 + (lane >> 2) + qr * 8;
                    int c0 = cl[nf][0];
                    float h0 = hold[mf][nf][qr][0], h1 = hold[mf][nf][qr][1];
                    float h0h = __bfloat162float(__float2bfloat16_rn(h0));
                    float h1h = __bfloat162float(__float2bfloat16_rn(h1));
                    int slab = c0 >> 6;
                    unsigned byte = (unsigned)(row * 128 + (c0 & 63) * 2);
                    unsigned sw = SW128(byte);
                    *(uint32_t*)(smem + EA_HI + slab * 4096 + sw) = pack2_bf16(h0h, h1h);
                    *(uint32_t*)(smem + EA_LO + slab * 4096 + sw) =
                        pack2_bf16(h0 - h0h, h1 - h1h);
                }
        __syncthreads();
    }

#pragma unroll
    for (int mf = 0; mf < 2; mf++)
#pragma unroll
        for (int qr = 0; qr < 2; qr++) {
            int row = mf * 16 + (lane >> 2) + qr * 8;
            if (row < E_RPB && b0 + row < BB) {
#pragma unroll
                for (int nf = 0; nf < 2; nf++) {
                    *(float2*)(g_ctx + (long)(b0 + row) * 128 + cl[nf][0]) =
                        make_float2(hold[mf][nf][qr][0], hold[mf][nf][qr][1]);
                }
            }
        }
}

// ---------------------------------------------------------------------------
// init
// ---------------------------------------------------------------------------
__global__ void init_kernel(const float* __restrict__ Whh, float* __restrict__ out) {
    const float4 one4 = make_float4(1.f, 1.f, 1.f, 1.f);
    int i = blockIdx.x * blockDim.x + threadIdx.x;
    if (i < BB * DH / 4) ((float4*)g_h)[i] = one4;
    if (i < BB * DH) {
        g_hb_hi[i] = __float2bfloat16(1.f);
        g_hb_lo[i] = __float2bfloat16(0.f);
    }
    if (i < 768 * DH) {
        float w = Whh[i];
        __nv_bfloat16 hi = __float2bfloat16(w);
        g_wb_hi[i] = hi;
        g_wb_lo[i] = __float2bfloat16(w - __bfloat162float(hi));
    }
    if (i < BB * 118) {
        int b = i / 118, tt = i % 118 + NDEC;
        *(float4*)(out + (long)b * (SS * 4) + tt * 4) = one4;
    }
}

// ---------------------------------------------------------------------------
// gi0 (once), scalar
// ---------------------------------------------------------------------------
#define NG 24
#define RPG 171
#define GI_WSTR 132
#define GI_SMEM_BYTES ((128 * GI_WSTR + 64 * 128) * 4)

__global__ void __launch_bounds__(256, 1)
dec_gi0_kernel(const float* __restrict__ Wih, const float* __restrict__ bih)
{
    extern __shared__ float sm[];
    float* Ws = sm;
    float* hs = sm + 128 * GI_WSTR;

    const int tid = threadIdx.x;
    const int s = blockIdx.x / NG;
    const int g = blockIdx.x % NG;
    const int r0 = g * RPG;
    const int nr = min(RPG, BB - r0);

    for (int u = tid; u < 128 * 128; u += 256) {
        int c = u >> 7, k = u & 127;
        Ws[c * GI_WSTR + k] = Wih[(long)(s * 128 + c) * 129 + k];
    }
    __syncthreads();

    const int rg = tid >> 5, cg = tid & 31;
    float bv[4];
#pragma unroll
    for (int m = 0; m < 4; m++) bv[m] = bih[s * 128 + cg + 32 * m];

    const int nchunk = (nr + 63) >> 6;
    for (int ch = 0; ch < nchunk; ++ch) {
        int rbase = ch * 64;
        for (int u = tid; u < 64 * 32; u += 256) {
            int r = u >> 5, q = u & 31;
            float4 v = make_float4(0.f, 0.f, 0.f, 0.f);
            if (rbase + r < nr)
                v = *(const float4*)(g_ctx + (long)(r0 + rbase + r) * 128 + q * 4);
            *(float4*)(hs + r * 128 + q * 4) = v;
        }
        __syncthreads();

        u64 acc[8][4];
#pragma unroll
        for (int i = 0; i < 8; i++)
#pragma unroll
            for (int m = 0; m < 4; m++) acc[i][m] = 0ULL;

#pragma unroll 2
        for (int kq = 0; kq < 32; ++kq) {
            ulonglong2 w[4];
#pragma unroll
            for (int m = 0; m < 4; m++)
                w[m] = *(const ulonglong2*)(Ws + (cg + 32 * m) * GI_WSTR + kq * 4);
#pragma unroll
            for (int i = 0; i < 8; i++) {
                ulonglong2 hv = *(const ulonglong2*)(hs + (rg * 8 + i) * 128 + kq * 4);
#pragma unroll
                for (int m = 0; m < 4; m++) {
                    ffma2(hv.x, w[m].x, acc[i][m]);
                    ffma2(hv.y, w[m].y, acc[i][m]);
                }
            }
        }
#pragma unroll
        for (int i = 0; i < 8; i++) {
            int row = rbase + rg * 8 + i;
            if (row < nr) {
#pragma unroll
                for (int m = 0; m < 4; m++)
                    g_gi0[(long)(r0 + row) * 768 + s * 128 + cg + 32 * m] =
                        f2sum(acc[i][m]) + bv[m];
            }
        }
        __syncthreads();
    }
}

// ---------------------------------------------------------------------------
// Decoder GEMM via mma.sync. R12: 512 threads / 16 warps (4 per SMSP) for
// latency cover (R10 profile: issue 8%, tensor 19%, L1 29% -> latency-bound).
// Block tile M=128 N=64 K=256; warp tile 32x16. Grid 32x12 = 384.
// ---------------------------------------------------------------------------
#define MM_STR 264
#define MM_A_HI 0
#define MM_A_LO (MM_A_HI + 128 * MM_STR * 2)
#define MM_B_HI (MM_A_LO + 128 * MM_STR * 2)
#define MM_B_LO (MM_B_HI + 64 * MM_STR * 2)
#define MM_SMEM_BYTES (MM_B_LO + 64 * MM_STR * 2)

__global__ void __launch_bounds__(512, 1)
dec_gemm_mma_kernel()
{
    extern __shared__ char smem[];
    const unsigned sb = smem_u32(smem);
    const int tid = threadIdx.x;
    const int lane = tid & 31;
    const int wid = tid >> 5;
    const int warp_m = wid & 3;        // 4 warps over M (32 rows each)
    const int warp_n = wid >> 2;       // 4 warps over N (16 cols each)
    const int mt = blockIdx.x & 31;
    const int nt = blockIdx.x >> 5;
    const int r0 = mt * 128;
    const int n0 = nt * 64;

    for (int u = tid; u < 128 * 32; u += 512) {
        int row = u >> 5, seg = u & 31;
        unsigned off = (unsigned)(row * (MM_STR * 2) + seg * 16);
        long src = (long)(r0 + row) * 256 + seg * 8;
        *(uint4*)(smem + MM_A_HI + off) = *(const uint4*)(g_hb_hi + src);
        *(uint4*)(smem + MM_A_LO + off) = *(const uint4*)(g_hb_lo + src);
    }
    for (int u = tid; u < 64 * 32; u += 512) {
        int row = u >> 5, seg = u & 31;
        unsigned off = (unsigned)(row * (MM_STR * 2) + seg * 16);
        long src = (long)(n0 + row) * 256 + seg * 8;
        *(uint4*)(smem + MM_B_HI + off) = *(const uint4*)(g_wb_hi + src);
        *(uint4*)(smem + MM_B_LO + off) = *(const uint4*)(g_wb_lo + src);
    }
    __syncthreads();

    float c[2][2][4];
#pragma unroll
    for (int mf = 0; mf < 2; mf++)
#pragma unroll
        for (int nf = 0; nf < 2; nf++)
#pragma unroll
            for (int q = 0; q < 4; q++) c[mf][nf][q] = 0.f;

    const unsigned a_row = (unsigned)(warp_m * 32 + (lane & 15));
    const unsigned a_half = (unsigned)((lane >> 4) * 16);
    const unsigned b_row = (unsigned)(warp_n * 16 + (lane & 7));
    const unsigned b_half = (unsigned)(((lane >> 3) & 1) * 16);

#pragma unroll 4
    for (int kk = 0; kk < 16; ++kk) {
        const unsigned koff = (unsigned)(kk * 32);
        uint32_t bh[2][2], bl[2][2];
#pragma unroll
        for (int nf = 0; nf < 2; nf++) {
            unsigned ba = (b_row + nf * 8) * (MM_STR * 2) + koff + b_half;
            ldsm_x2(bh[nf], sb + MM_B_HI + ba);
            ldsm_x2(bl[nf], sb + MM_B_LO + ba);
        }
#pragma unroll
        for (int mf = 0; mf < 2; mf++) {
            unsigned aa = (a_row + mf * 16) * (MM_STR * 2) + koff + a_half;
            uint32_t ah[4], al[4];
            ldsm_x4(ah, sb + MM_A_HI + aa);
            ldsm_x4(al, sb + MM_A_LO + aa);
#pragma unroll
            for (int nf = 0; nf < 2; nf++) {
                mma_bf16(c[mf][nf], ah, bh[nf]);
                mma_bf16(c[mf][nf], ah, bl[nf]);
                mma_bf16(c[mf][nf], al, bh[nf]);
            }
        }
    }

#pragma unroll
    for (int mf = 0; mf < 2; mf++) {
#pragma unroll
        for (int nf = 0; nf < 2; nf++) {
            int row = r0 + warp_m * 32 + mf * 16 + (lane >> 2);
            int col = n0 + warp_n * 16 + nf * 8 + (lane & 3) * 2;
            *(float2*)(g_gates + (long)row * 768 + col) =
                make_float2(c[mf][nf][0], c[mf][nf][1]);
            *(float2*)(g_gates + (long)(row + 8) * 768 + col) =
                make_float2(c[mf][nf][2], c[mf][nf][3]);
        }
    }
}

// ---------------------------------------------------------------------------
// pointwise
// ---------------------------------------------------------------------------
__global__ void __launch_bounds__(256, 1)
dec_point_kernel(const float* __restrict__ y, const float* __restrict__ Wih,
                 const float* __restrict__ bhh, const float* __restrict__ linW,
                 const float* __restrict__ linb, float* __restrict__ out, int t)
{
    __shared__ float hs[32 * 256];
    __shared__ float ys[32];
    __shared__ float lw[1024];
    __shared__ float lb[4];

    const int tid = threadIdx.x;
    const int b0 = blockIdx.x * 32;

    if (tid < 32) ys[tid] = y[(long)(b0 + tid) * SS + t];
    for (int u = tid; u < 1024; u += 256) lw[u] = linW[u];
    if (tid < 4) lb[tid] = linb[tid];

    const int c = tid;
    const float wyr = Wih[(long)c * 129 + 128];
    const float wyz = Wih[(long)(c + 256) * 129 + 128];
    const float wyn = Wih[(long)(c + 512) * 129 + 128];
    const float br = bhh[c], bz = bhh[c + 256], bn = bhh[c + 512];
    __syncthreads();

#pragma unroll 4
    for (int r = 0; r < 32; ++r) {
        long b = b0 + r;
        float yv = ys[r];
        float gr  = g_gi0[b * 768 + c]       + yv * wyr + g_gates[b * 768 + c]       + br;
        float gz  = g_gi0[b * 768 + c + 256] + yv * wyz + g_gates[b * 768 + c + 256] + bz;
        float gni = g_gi0[b * 768 + c + 512] + yv * wyn;
        float gnh = g_gates[b * 768 + c + 512] + bn;
        float rr = sigf(gr);
        float zz = sigf(gz);
        float nn = tanhfast(gni + rr * gnh);
        float h  = g_h[b * 256 + c];
        float hn = (1.f - zz) * nn + zz * h;
        g_h[b * 256 + c] = hn;
        __nv_bfloat16 hi = __float2bfloat16(hn);
        g_hb_hi[b * 256 + c] = hi;
        g_hb_lo[b * 256 + c] = __float2bfloat16(hn - __bfloat162float(hi));
        hs[r * 256 + c] = hn;
    }
    __syncthreads();

    if (tid < 128) {
        int r = tid >> 2, o = tid & 3;
        float s = lb[o];
#pragma unroll 4
        for (int q = 0; q < 64; ++q) {
            float4 hv = *(float4*)(hs + r * 256 + q * 4);
            float4 wv = *(float4*)(lw + o * 256 + q * 4);
            s += hv.x * wv.x + hv.y * wv.y + hv.z * wv.z + hv.w * wv.w;
        }
        out[(long)(b0 + r) * (SS * 4) + t * 4 + o] = s;
    }
}

extern "C" void kernel_launch(void* const* d_in, const int* in_sizes, int n_in,
                              void* d_out, int out_size) {
    const float* x    = (const float*)d_in[0];
    const float* y    = (const float*)d_in[1];
    const float* eWih = (const float*)d_in[2];
    const float* eWhh = (const float*)d_in[3];
    const float* ebih = (const float*)d_in[4];
    const float* ebhh = (const float*)d_in[5];
    const float* dWih = (const float*)d_in[6];
    const float* dWhh = (const float*)d_in[7];
    const float* dbih = (const float*)d_in[8];
    const float* dbhh = (const float*)d_in[9];
    const float* lW   = (const float*)d_in[10];
    const float* lb   = (const float*)d_in[11];
    float* out = (float*)d_out;

    cudaFuncSetAttribute(enc_tc_kernel, cudaFuncAttributeMaxDynamicSharedMemorySize,
                         E2_SMEM_BYTES);
    cudaFuncSetAttribute(dec_gi0_kernel, cudaFuncAttributeMaxDynamicSharedMemorySize,
                         GI_SMEM_BYTES);
    cudaFuncSetAttribute(dec_gemm_mma_kernel, cudaFuncAttributeMaxDynamicSharedMemorySize,
                         MM_SMEM_BYTES);

    init_kernel<<<BB, 256>>>(dWhh, out);
    enc_tc_kernel<<<(BB + E_RPB - 1) / E_RPB, 256, E2_SMEM_BYTES>>>(
        x, eWih, eWhh, ebih, ebhh);
    dec_gi0_kernel<<<6 * NG, 256, GI_SMEM_BYTES>>>(dWih, dbih);
    for (int t = 0; t < NDEC; ++t) {
        dec_gemm_mma_kernel<<<384, 512, MM_SMEM_BYTES>>>();
        dec_point_kernel<<<BB / 32, 256>>>(y, dWih, dbhh, lW, lb, out, t);
    }
}